// round 12
// baseline (speedup 1.0000x reference)
#include <cuda_runtime.h>
#include <math.h>

#define B_ 2
#define S_ 2048
#define D_ 1024
#define H_ 16
#define DH_ 64
#define DR_ 64
#define DL_ 512
#define DHID_ 512
#define NR_ 8
#define NS_ 2
#define T_ (B_*S_)          // 4096 tokens
#define QDIM_ (DH_+DR_)     // 128

// ---------------- scratch (device globals; no allocation allowed) ----------
__device__ float g_h  [T_*D_];
__device__ float g_q  [T_*H_*QDIM_];
__device__ float g_lat[T_*DL_];
__device__ float g_kc [T_*H_*DH_];
__device__ float g_v  [T_*H_*DH_];
__device__ float g_kr [T_*DR_];
__device__ float g_ctx[T_*H_*DH_];
__device__ float g_h2 [T_*D_];
__device__ int   g_cnt[NR_];
__device__ int   g_elist[NR_*T_];
__device__ int   g_rt  [T_*4];        // per-token (e1,pos1,e2,pos2)
__device__ float g_rw  [T_*2];        // per-token (w1,w2)
// shared experts
__device__ float g_gsh[NS_*T_*DHID_];
__device__ float g_ush[NS_*T_*DHID_];
__device__ float g_ysh[NS_*T_*D_];
// routed experts (compact per-expert regions, stride T_ rows)
__device__ float g_gb [NR_*T_*DHID_];
__device__ float g_ub [NR_*T_*DHID_];
__device__ float g_y  [NR_*T_*D_];

__device__ __forceinline__ unsigned f2tf(float x) {
    unsigned r;
    asm("cvt.rna.tf32.f32 %0, %1;" : "=r"(r) : "f"(x));
    return r;
}

__device__ __forceinline__ void cp16(float* dst, const float* src) {
    unsigned d = (unsigned)__cvta_generic_to_shared(dst);
    asm volatile("cp.async.cg.shared.global [%0], [%1], 16;" :: "r"(d), "l"(src));
}

// ---------------- rmsnorm --------------------------------------------------
__global__ void rmsnorm_k(const float* __restrict__ x, const float* __restrict__ w,
                          float* __restrict__ o) {
    int row = blockIdx.x;
    const float* xr = x + (size_t)row * D_;
    float ss = 0.f;
    float vloc[4];
#pragma unroll
    for (int i = 0; i < 4; i++) { vloc[i] = xr[threadIdx.x + i*256]; ss += vloc[i]*vloc[i]; }
#pragma unroll
    for (int off = 16; off; off >>= 1) ss += __shfl_xor_sync(0xffffffffu, ss, off);
    __shared__ float sm[8];
    __shared__ float invs;
    if ((threadIdx.x & 31) == 0) sm[threadIdx.x >> 5] = ss;
    __syncthreads();
    if (threadIdx.x == 0) {
        float t = 0.f;
#pragma unroll
        for (int i = 0; i < 8; i++) t += sm[i];
        invs = 1.0f / sqrtf(t / (float)D_ + 1e-6f);
    }
    __syncthreads();
    float inv = invs;
    float* orow = o + (size_t)row * D_;
#pragma unroll
    for (int i = 0; i < 4; i++) {
        int d = threadIdx.x + i*256;
        orow[d] = vloc[i] * inv * w[d];
    }
}

// ------- tf32 mma core: 128x128x32 k-tiles, 2-stage cp.async ---------------
#define STG_ 2
#define KT_ 32
#define SA_STRIDE 36                 // 32 k + 4 pad (banks (4r+cq)%32 distinct)
#define SB_STRIDE 136                // 128 n + 8 pad
#define SA_SZ (128*SA_STRIDE)        // 4608 floats per stage (A)
#define SB_SZ (32*SB_STRIDE)         // 4352 floats per stage (B)
#define STG_SZ (SA_SZ + SB_SZ)       // 8960
#define MM_SMEM_BYTES (STG_*STG_SZ*4)   // 71,680 B

// cnt < 0 : dense. cnt >= 0: rows bounded by cnt (clamped loads, guarded writes).
// idx != null: A rows gathered via idx. C rows always compact (= global row).
// Dadd != null: C = Dadd + acc. N may be < 128 (multiple of 8).
__device__ __forceinline__ void mma_core(
        const float* __restrict__ A, const float* __restrict__ Bm,
        float* __restrict__ C, int N, int K, int bx, int by,
        int cnt, const int* __restrict__ idx, const float* __restrict__ Dadd) {
    extern __shared__ float smdyn[];

    int tid = threadIdx.x;
    int warp = tid >> 5, lane = tid & 31;
    int wm = warp & 3;
    int wn = warp >> 2;
    int r  = lane >> 2;
    int cq = lane & 3;

    float acc[2][8][4];
#pragma unroll
    for (int i = 0; i < 2; i++)
#pragma unroll
        for (int j = 0; j < 8; j++)
#pragma unroll
            for (int k = 0; k < 4; k++) acc[i][j][k] = 0.f;

    // A loader: thread -> row ar (0..127), k-offset ak (0 or 16), 4 cp16
    int ar = tid >> 1;
    int ak = (tid & 1) * 16;
    int gRowA = by*128 + ar;
    int rowA;
    if (idx) {
        int rs = (cnt >= 0 && gRowA >= cnt) ? (cnt - 1) : gRowA;
        rowA = idx[rs];
    } else if (cnt >= 0) {
        rowA = (gRowA < cnt) ? gRowA : (cnt - 1);
    } else {
        rowA = gRowA;
    }
    const float* Arow = A + (size_t)rowA * K + ak;
    int aDst = ar*SA_STRIDE + ak;

    // B loader: thread -> k-rows br and br+16, n-offset bc, 2 cp16 each
    int br = tid >> 4;
    int bc = (tid & 15) * 8;
    int bcc = (bc + 8 <= N) ? bc : (N - 8);     // src clamp for N<128
    const float* Bsrc0 = Bm + (size_t)br * N + (size_t)bx*128 + bcc;
    int bDst0 = SA_SZ + br*SB_STRIDE + bc;
    int bDst1 = SA_SZ + (br+16)*SB_STRIDE + bc;

    int ntiles = K >> 5;

    // prologue: tile 0 into stage 0
    {
        float* st = smdyn;
        const float* as = Arow;
        cp16(st + aDst,      as);
        cp16(st + aDst + 4,  as + 4);
        cp16(st + aDst + 8,  as + 8);
        cp16(st + aDst + 12, as + 12);
        const float* bs = Bsrc0;
        cp16(st + bDst0,     bs);
        cp16(st + bDst0 + 4, bs + 4);
        const float* bs1 = bs + (size_t)16 * N;
        cp16(st + bDst1,     bs1);
        cp16(st + bDst1 + 4, bs1 + 4);
        asm volatile("cp.async.commit_group;");
    }

    for (int kt = 0; kt < ntiles; kt++) {
        asm volatile("cp.async.wait_group 0;");
        __syncthreads();   // tile kt resident; all warps done reading stage (kt+1)&1

        if (kt + 1 < ntiles) {      // prefetch next tile into the other stage
            float* st = smdyn + ((kt+1) & 1)*STG_SZ;
            const float* as = Arow + (size_t)(kt+1)*KT_;
            cp16(st + aDst,      as);
            cp16(st + aDst + 4,  as + 4);
            cp16(st + aDst + 8,  as + 8);
            cp16(st + aDst + 12, as + 12);
            const float* bs = Bsrc0 + (size_t)(kt+1) * KT_ * N;
            cp16(st + bDst0,     bs);
            cp16(st + bDst0 + 4, bs + 4);
            const float* bs1 = bs + (size_t)16 * N;
            cp16(st + bDst1,     bs1);
            cp16(st + bDst1 + 4, bs1 + 4);
            asm volatile("cp.async.commit_group;");
        }

        const unsigned* As = (const unsigned*)(smdyn + (kt & 1)*STG_SZ);
        const unsigned* Bs = As + SA_SZ;

#pragma unroll
        for (int kk = 0; kk < KT_; kk += 8) {
            unsigned a[2][4];
#pragma unroll
            for (int i = 0; i < 2; i++) {
                int m0 = (wm*32 + i*16 + r) * SA_STRIDE;
                a[i][0] = As[m0                + kk + cq];
                a[i][1] = As[m0 + 8*SA_STRIDE  + kk + cq];
                a[i][2] = As[m0                + kk + cq + 4];
                a[i][3] = As[m0 + 8*SA_STRIDE  + kk + cq + 4];
            }
#pragma unroll
            for (int j = 0; j < 8; j++) {
                int n0 = wn*64 + j*8 + r;
                unsigned b0 = Bs[(kk+cq  )*SB_STRIDE + n0];
                unsigned b1 = Bs[(kk+cq+4)*SB_STRIDE + n0];
#pragma unroll
                for (int i = 0; i < 2; i++) {
                    asm volatile(
                        "mma.sync.aligned.m16n8k8.row.col.f32.tf32.tf32.f32 "
                        "{%0,%1,%2,%3},{%4,%5,%6,%7},{%8,%9},{%0,%1,%2,%3};"
                        : "+f"(acc[i][j][0]), "+f"(acc[i][j][1]),
                          "+f"(acc[i][j][2]), "+f"(acc[i][j][3])
                        : "r"(a[i][0]), "r"(a[i][1]), "r"(a[i][2]), "r"(a[i][3]),
                          "r"(b0), "r"(b1));
                }
            }
        }
    }

#pragma unroll
    for (int i = 0; i < 2; i++) {
        int lrow = wm*32 + i*16 + r;
        int gr0 = by*128 + lrow;
        int gr1 = gr0 + 8;
#pragma unroll
        for (int half = 0; half < 2; half++) {
            int gr = half ? gr1 : gr0;
            if (cnt >= 0 && gr >= cnt) continue;
            float* cbase = C + (size_t)gr * N + (size_t)bx*128 + wn*64;
            const float* dbase = Dadd ? (Dadd + (size_t)gr * N + (size_t)bx*128 + wn*64)
                                      : nullptr;
#pragma unroll
            for (int j = 0; j < 8; j++) {
                int ncol = wn*64 + j*8 + cq*2;
                if (bx*128 + ncol >= N && N < 128) continue;  // N<128 guard
                float v0 = acc[i][j][half*2 + 0];
                float v1 = acc[i][j][half*2 + 1];
                float2* p = (float2*)(cbase + j*8 + cq*2);
                if (dbase) {
                    float2 dv = *(const float2*)(dbase + j*8 + cq*2);
                    float2 nv; nv.x = dv.x + v0; nv.y = dv.y + v1;
                    *p = nv;
                } else {
                    float2 nv; nv.x = v0; nv.y = v1;
                    *p = nv;
                }
            }
        }
    }
}

// ---- dense multi-segment (same A, up to 4 (B,C,N) segments along grid.x) --
__global__ __launch_bounds__(256, 2) void mma_multi4(
        const float* __restrict__ A, int K,
        const float* B0, float* C0, int N0, int X0,
        const float* B1, float* C1, int N1, int X1,
        const float* B2, float* C2, int N2, int X2,
        const float* B3, float* C3, int N3, int X3,
        const float* __restrict__ Dadd) {
    int bx = blockIdx.x;
    const float* Bm; float* C; int N;
    if (bx < X0)                { Bm = B0; C = C0; N = N0; }
    else if (bx < X0+X1)        { bx -= X0; Bm = B1; C = C1; N = N1; }
    else if (bx < X0+X1+X2)     { bx -= X0+X1; Bm = B2; C = C2; N = N2; }
    else                        { bx -= X0+X1+X2; Bm = B3; C = C3; N = N3; }
    mma_core(A, Bm, C, N, K, bx, blockIdx.y, -1, nullptr, Dadd);
}

// ---- routed experts: gate+up batched over z=expert, gathered A ------------
__global__ __launch_bounds__(256, 2) void mma_gu_routed(
        const float* __restrict__ h2, const float* __restrict__ wr_gate,
        const float* __restrict__ wr_up, float* __restrict__ gb,
        float* __restrict__ ub, const int* __restrict__ elist,
        const int* __restrict__ cntArr) {
    int e = blockIdx.z;
    int cnt = cntArr[e];
    if ((int)blockIdx.y * 128 >= cnt) return;
    int bx = blockIdx.x;
    const float* Bm; float* C;
    if (bx < DHID_/128) { Bm = wr_gate + (size_t)e*D_*DHID_; C = gb + (size_t)e*T_*DHID_; }
    else { bx -= DHID_/128; Bm = wr_up + (size_t)e*D_*DHID_; C = ub + (size_t)e*T_*DHID_; }
    mma_core(h2, Bm, C, DHID_, D_, bx, blockIdx.y, cnt, elist + e*T_, nullptr);
}

// ---- routed experts: down batched, compact in -> compact out --------------
__global__ __launch_bounds__(256, 2) void mma_down_routed(
        const float* __restrict__ gb, const float* __restrict__ wr_down,
        float* __restrict__ y, const int* __restrict__ cntArr) {
    int e = blockIdx.z;
    int cnt = cntArr[e];
    if ((int)blockIdx.y * 128 >= cnt) return;
    mma_core(gb + (size_t)e*T_*DHID_, wr_down + (size_t)e*DHID_*D_,
             y + (size_t)e*T_*D_, D_, DHID_, blockIdx.x, blockIdx.y,
             cnt, nullptr, nullptr);
}

// ---- shared experts: down batched over z ----------------------------------
__global__ __launch_bounds__(256, 2) void mma_down_shared(
        const float* __restrict__ gsh, const float* __restrict__ ws_down,
        float* __restrict__ ysh) {
    int s = blockIdx.z;
    mma_core(gsh + (size_t)s*T_*DHID_, ws_down + (size_t)s*DHID_*D_,
             ysh + (size_t)s*T_*D_, D_, DHID_, blockIdx.x, blockIdx.y,
             -1, nullptr, nullptr);
}

// ---------------- RoPE (in-place on q tail + k_r) --------------------------
__global__ void rope_k(float* __restrict__ q, float* __restrict__ kr) {
    int p = blockIdx.x * blockDim.x + threadIdx.x;
    const int NQ = T_ * H_ * 32;
    const int NK = T_ * 32;
    if (p < NQ) {
        int i = p & 31;
        int h = (p >> 5) & (H_ - 1);
        int t = p >> 9;
        int s = t & (S_ - 1);
        float inv = powf(10000.0f, -(float)i / 32.0f);
        float sn, c;
        sincosf((float)s * inv, &sn, &c);
        float* base = q + (size_t)t * (H_*QDIM_) + h * QDIM_ + DH_;
        float t1 = base[i], t2 = base[32 + i];
        base[i]      = t1 * c - t2 * sn;
        base[32 + i] = t2 * c + t1 * sn;
    } else if (p < NQ + NK) {
        int p2 = p - NQ;
        int i = p2 & 31;
        int t = p2 >> 5;
        int s = t & (S_ - 1);
        float inv = powf(10000.0f, -(float)i / 32.0f);
        float sn, c;
        sincosf((float)s * inv, &sn, &c);
        float* base = kr + (size_t)t * DR_;
        float t1 = base[i], t2 = base[32 + i];
        base[i]      = t1 * c - t2 * sn;
        base[32 + i] = t2 * c + t1 * sn;
    }
}

// ---------------- tensor-core flash attention (causal, d=128, dv=64) -------
#define FA_SMEM_FLOATS (64*132 + 64*132 + 64*68 + 4*16*68)
#define FA_SMEM_BYTES  (FA_SMEM_FLOATS*4)

__global__ __launch_bounds__(128) void flash_mma_k(
        const float* __restrict__ q, const float* __restrict__ kc,
        const float* __restrict__ kr, const float* __restrict__ v,
        float* __restrict__ ctx) {
    extern __shared__ unsigned smbuf[];
    unsigned* Qs = smbuf;                 // [64][132]
    unsigned* Ks = Qs + 64*132;           // [64][132]
    unsigned* Vs = Ks + 64*132;           // [64][68]
    unsigned* Ps = Vs + 64*68;            // [4][16][68]

    int qb = blockIdx.x;
    int bh = blockIdx.y;
    int b = bh >> 4, h = bh & 15;
    int tid = threadIdx.x;
    int warp = tid >> 5, lane = tid & 31;
    int r = lane >> 2, cq = lane & 3;
    size_t tq = (size_t)b*S_ + qb*64;
    unsigned* Pw = Ps + warp*16*68;

#pragma unroll
    for (int i = 0; i < 16; i++) {
        int e = i*128 + tid;
        int row = e >> 5, c4 = (e & 31) * 4;
        float4 qv = *(const float4*)&q[(tq+row)*(size_t)(H_*QDIM_) + h*QDIM_ + c4];
        unsigned* dst = &Qs[row*132 + c4];
        dst[0]=f2tf(qv.x); dst[1]=f2tf(qv.y); dst[2]=f2tf(qv.z); dst[3]=f2tf(qv.w);
    }

    float m0 = -1e30f, m1 = -1e30f;
    float l0 = 0.f,  l1 = 0.f;
    float o[8][4];
#pragma unroll
    for (int j = 0; j < 8; j++)
#pragma unroll
        for (int k = 0; k < 4; k++) o[j][k] = 0.f;

    const float scale = 0.088388347648318447f;   // 1/sqrt(128)
    int nkb = qb + 1;

    for (int kb = 0; kb < nkb; kb++) {
        size_t tk = (size_t)b*S_ + kb*64;
        __syncthreads();
#pragma unroll
        for (int i = 0; i < 8; i++) {
            int e = i*128 + tid;
            int row = e >> 4, c4 = (e & 15) * 4;
            float4 kv = *(const float4*)&kc[(tk+row)*(size_t)(H_*DH_) + h*DH_ + c4];
            unsigned* dst = &Ks[row*132 + c4];
            dst[0]=f2tf(kv.x); dst[1]=f2tf(kv.y); dst[2]=f2tf(kv.z); dst[3]=f2tf(kv.w);
        }
#pragma unroll
        for (int i = 0; i < 8; i++) {
            int e = i*128 + tid;
            int row = e >> 4, c4 = (e & 15) * 4;
            float4 kv = *(const float4*)&kr[(tk+row)*(size_t)DR_ + c4];
            unsigned* dst = &Ks[row*132 + 64 + c4];
            dst[0]=f2tf(kv.x); dst[1]=f2tf(kv.y); dst[2]=f2tf(kv.z); dst[3]=f2tf(kv.w);
        }
#pragma unroll
        for (int i = 0; i < 8; i++) {
            int e = i*128 + tid;
            int row = e >> 4, c4 = (e & 15) * 4;
            float4 vv = *(const float4*)&v[(tk+row)*(size_t)(H_*DH_) + h*DH_ + c4];
            unsigned* dst = &Vs[row*68 + c4];
            dst[0]=f2tf(vv.x); dst[1]=f2tf(vv.y); dst[2]=f2tf(vv.z); dst[3]=f2tf(vv.w);
        }
        __syncthreads();

        float s[8][4];
#pragma unroll
        for (int j = 0; j < 8; j++)
#pragma unroll
            for (int k = 0; k < 4; k++) s[j][k] = 0.f;

#pragma unroll
        for (int kk = 0; kk < 128; kk += 8) {
            int m0r = (warp*16 + r)*132;
            unsigned a0 = Qs[m0r + kk + cq];
            unsigned a1 = Qs[m0r + 8*132 + kk + cq];
            unsigned a2 = Qs[m0r + kk + cq + 4];
            unsigned a3 = Qs[m0r + 8*132 + kk + cq + 4];
#pragma unroll
            for (int j = 0; j < 8; j++) {
                unsigned b0 = Ks[(j*8 + r)*132 + kk + cq];
                unsigned b1 = Ks[(j*8 + r)*132 + kk + cq + 4];
                asm volatile(
                    "mma.sync.aligned.m16n8k8.row.col.f32.tf32.tf32.f32 "
                    "{%0,%1,%2,%3},{%4,%5,%6,%7},{%8,%9},{%0,%1,%2,%3};"
                    : "+f"(s[j][0]), "+f"(s[j][1]), "+f"(s[j][2]), "+f"(s[j][3])
                    : "r"(a0), "r"(a1), "r"(a2), "r"(a3), "r"(b0), "r"(b1));
            }
        }

        bool diag = (kb == qb);
        int lq0 = warp*16 + r;
        int lq1 = lq0 + 8;
#pragma unroll
        for (int j = 0; j < 8; j++) {
            int c0 = j*8 + cq*2, c1 = c0 + 1;
            s[j][0] *= scale; s[j][1] *= scale;
            s[j][2] *= scale; s[j][3] *= scale;
            if (diag) {
                if (c0 > lq0) s[j][0] = -1e9f;
                if (c1 > lq0) s[j][1] = -1e9f;
                if (c0 > lq1) s[j][2] = -1e9f;
                if (c1 > lq1) s[j][3] = -1e9f;
            }
        }

        float mt0 = -1e30f, mt1 = -1e30f;
#pragma unroll
        for (int j = 0; j < 8; j++) {
            mt0 = fmaxf(mt0, fmaxf(s[j][0], s[j][1]));
            mt1 = fmaxf(mt1, fmaxf(s[j][2], s[j][3]));
        }
        mt0 = fmaxf(mt0, __shfl_xor_sync(0xffffffffu, mt0, 1));
        mt0 = fmaxf(mt0, __shfl_xor_sync(0xffffffffu, mt0, 2));
        mt1 = fmaxf(mt1, __shfl_xor_sync(0xffffffffu, mt1, 1));
        mt1 = fmaxf(mt1, __shfl_xor_sync(0xffffffffu, mt1, 2));

        float mn0 = fmaxf(m0, mt0), mn1 = fmaxf(m1, mt1);
        float al0 = __expf(m0 - mn0), al1 = __expf(m1 - mn1);
        m0 = mn0; m1 = mn1;

        float ps0 = 0.f, ps1 = 0.f;
#pragma unroll
        for (int j = 0; j < 8; j++) {
            s[j][0] = __expf(s[j][0] - mn0);
            s[j][1] = __expf(s[j][1] - mn0);
            s[j][2] = __expf(s[j][2] - mn1);
            s[j][3] = __expf(s[j][3] - mn1);
            ps0 += s[j][0] + s[j][1];
            ps1 += s[j][2] + s[j][3];
        }
        ps0 += __shfl_xor_sync(0xffffffffu, ps0, 1);
        ps0 += __shfl_xor_sync(0xffffffffu, ps0, 2);
        ps1 += __shfl_xor_sync(0xffffffffu, ps1, 1);
        ps1 += __shfl_xor_sync(0xffffffffu, ps1, 2);
        l0 = l0 * al0 + ps0;
        l1 = l1 * al1 + ps1;

#pragma unroll
        for (int j = 0; j < 8; j++) {
            o[j][0] *= al0; o[j][1] *= al0;
            o[j][2] *= al1; o[j][3] *= al1;
        }

#pragma unroll
        for (int j = 0; j < 8; j++) {
            int c0 = j*8 + cq*2;
            Pw[r*68 + c0]       = f2tf(s[j][0]);
            Pw[r*68 + c0 + 1]   = f2tf(s[j][1]);
            Pw[(r+8)*68 + c0]     = f2tf(s[j][2]);
            Pw[(r+8)*68 + c0 + 1] = f2tf(s[j][3]);
        }
        __syncwarp();

#pragma unroll
        for (int kk = 0; kk < 64; kk += 8) {
            unsigned a0 = Pw[r*68 + kk + cq];
            unsigned a1 = Pw[(r+8)*68 + kk + cq];
            unsigned a2 = Pw[r*68 + kk + cq + 4];
            unsigned a3 = Pw[(r+8)*68 + kk + cq + 4];
#pragma unroll
            for (int j = 0; j < 8; j++) {
                unsigned b0 = Vs[(kk+cq)*68 + j*8 + r];
                unsigned b1 = Vs[(kk+cq+4)*68 + j*8 + r];
                asm volatile(
                    "mma.sync.aligned.m16n8k8.row.col.f32.tf32.tf32.f32 "
                    "{%0,%1,%2,%3},{%4,%5,%6,%7},{%8,%9},{%0,%1,%2,%3};"
                    : "+f"(o[j][0]), "+f"(o[j][1]), "+f"(o[j][2]), "+f"(o[j][3])
                    : "r"(a0), "r"(a1), "r"(a2), "r"(a3), "r"(b0), "r"(b1));
            }
        }
        __syncwarp();
    }

    float inv0 = 1.f / l0, inv1 = 1.f / l1;
    size_t row0 = (tq + warp*16 + r) * (size_t)(H_*DH_) + h*DH_;
    size_t row1 = row0 + (size_t)8 * (H_*DH_);
#pragma unroll
    for (int j = 0; j < 8; j++) {
        int c0 = j*8 + cq*2;
        float2 v0; v0.x = o[j][0]*inv0; v0.y = o[j][1]*inv0;
        float2 v1; v1.x = o[j][2]*inv1; v1.y = o[j][3]*inv1;
        *(float2*)&ctx[row0 + c0] = v0;
        *(float2*)&ctx[row1 + c0] = v1;
    }
}

// ---------------- misc elementwise ----------------------------------------
__global__ void zero_cnt_k(int* c) {
    if (threadIdx.x < NR_) c[threadIdx.x] = 0;
}

// z = blockIdx.y selects slice; cntArr null => dense (cnt = T_)
__global__ void silu_batched_k(const float* __restrict__ g, const float* __restrict__ u,
                               float* __restrict__ o, const int* __restrict__ cntArr) {
    int z = blockIdx.y;
    int cnt = cntArr ? cntArr[z] : T_;
    long i = (long)blockIdx.x * blockDim.x + threadIdx.x;
    if (i >= (long)cnt * DHID_) return;
    size_t base = (size_t)z * T_ * DHID_;
    float gv = g[base + i], uv = u[base + i];
    o[base + i] = (gv / (1.f + __expf(-gv))) * uv;
}

// ---------------- gating: logits + softmax + top2 + routing ----------------
__global__ void gate_topk_k(const float* __restrict__ h2, const float* __restrict__ gw,
                            int* __restrict__ cnt, int* __restrict__ elist,
                            int* __restrict__ rt, float* __restrict__ rw) {
    int t = blockIdx.x * 8 + (threadIdx.x >> 5);
    int lane = threadIdx.x & 31;
    if (t >= T_) return;
    float acc[NR_];
#pragma unroll
    for (int e = 0; e < NR_; e++) acc[e] = 0.f;
    const float* hr = h2 + (size_t)t * D_;
    for (int d = lane; d < D_; d += 32) {
        float xv = hr[d];
        const float* g = gw + (size_t)d * NR_;
#pragma unroll
        for (int e = 0; e < NR_; e++) acc[e] += xv * g[e];
    }
#pragma unroll
    for (int e = 0; e < NR_; e++)
#pragma unroll
        for (int off = 16; off; off >>= 1)
            acc[e] += __shfl_xor_sync(0xffffffffu, acc[e], off);
    if (lane == 0) {
        int i1 = 0;
#pragma unroll
        for (int e = 1; e < NR_; e++) if (acc[e] > acc[i1]) i1 = e;
        int i2 = (i1 == 0) ? 1 : 0;
#pragma unroll
        for (int e = 0; e < NR_; e++) {
            if (e == i1 || e == i2) continue;
            if (acc[e] > acc[i2]) i2 = e;
        }
        float p2 = __expf(acc[i2] - acc[i1]);
        float inv = 1.f / (1.f + p2);
        float w1 = inv, w2 = p2 * inv;
        int pos1 = atomicAdd(&cnt[i1], 1);
        elist[i1*T_ + pos1] = t;
        int pos2 = atomicAdd(&cnt[i2], 1);
        elist[i2*T_ + pos2] = t;
        rt[t*4+0] = i1; rt[t*4+1] = pos1;
        rt[t*4+2] = i2; rt[t*4+3] = pos2;
        rw[t*2+0] = w1; rw[t*2+1] = w2;
    }
}

// ---------------- final reduce: out += shared + routed ---------------------
__global__ void reduce_k(float* __restrict__ out, const float* __restrict__ ysh,
                         const float* __restrict__ y, const int* __restrict__ rt,
                         const float* __restrict__ rw) {
    int t = blockIdx.x;
    int tid = threadIdx.x;
    int e1 = rt[t*4+0], p1 = rt[t*4+1];
    int e2 = rt[t*4+2], p2 = rt[t*4+3];
    float w1 = rw[t*2+0], w2 = rw[t*2+1];
    const float4* s0 = (const float4*)(ysh + (size_t)t * D_);
    const float4* s1 = (const float4*)(ysh + ((size_t)T_ + t) * D_);
    const float4* y1 = (const float4*)(y + ((size_t)e1*T_ + p1) * D_);
    const float4* y2 = (const float4*)(y + ((size_t)e2*T_ + p2) * D_);
    float4* op = (float4*)(out + (size_t)t * D_);
    for (int d = tid; d < D_/4; d += blockDim.x) {
        float4 o = op[d];
        float4 a = s0[d], b = s1[d], c = y1[d], e = y2[d];
        o.x += a.x + b.x + w1*c.x + w2*e.x;
        o.y += a.y + b.y + w1*c.y + w2*e.y;
        o.z += a.z + b.z + w1*c.z + w2*e.z;
        o.w += a.w + b.w + w1*c.w + w2*e.w;
        op[d] = o;
    }
}

// ---------------- launch ---------------------------------------------------
extern "C" void kernel_launch(void* const* d_in, const int* in_sizes, int n_in,
                              void* d_out, int out_size) {
    const float* x         = (const float*)d_in[0];
    const float* w_q       = (const float*)d_in[2];
    const float* w_dkv     = (const float*)d_in[3];
    const float* w_uk      = (const float*)d_in[4];
    const float* w_uv      = (const float*)d_in[5];
    const float* w_kr      = (const float*)d_in[6];
    const float* w_o       = (const float*)d_in[7];
    const float* attn_nw   = (const float*)d_in[8];
    const float* mlp_nw    = (const float*)d_in[9];
    const float* gate_w    = (const float*)d_in[10];
    const float* wr_gate   = (const float*)d_in[11];
    const float* wr_up     = (const float*)d_in[12];
    const float* wr_down   = (const float*)d_in[13];
    const float* ws_gate   = (const float*)d_in[14];
    const float* ws_up     = (const float*)d_in[15];
    const float* ws_down   = (const float*)d_in[16];
    float* out = (float*)d_out;

    float *ph, *pq, *plat, *pkc, *pv, *pkr, *pctx, *ph2;
    float *pgsh, *push, *pysh, *pgb, *pub, *py, *prw;
    int *pcnt, *pel, *prt;
    cudaGetSymbolAddress((void**)&ph,   g_h);
    cudaGetSymbolAddress((void**)&pq,   g_q);
    cudaGetSymbolAddress((void**)&plat, g_lat);
    cudaGetSymbolAddress((void**)&pkc,  g_kc);
    cudaGetSymbolAddress((void**)&pv,   g_v);
    cudaGetSymbolAddress((void**)&pkr,  g_kr);
    cudaGetSymbolAddress((void**)&pctx, g_ctx);
    cudaGetSymbolAddress((void**)&ph2,  g_h2);
    cudaGetSymbolAddress((void**)&pgsh, g_gsh);
    cudaGetSymbolAddress((void**)&push, g_ush);
    cudaGetSymbolAddress((void**)&pysh, g_ysh);
    cudaGetSymbolAddress((void**)&pgb,  g_gb);
    cudaGetSymbolAddress((void**)&pub,  g_ub);
    cudaGetSymbolAddress((void**)&py,   g_y);
    cudaGetSymbolAddress((void**)&pcnt, g_cnt);
    cudaGetSymbolAddress((void**)&pel,  g_elist);
    cudaGetSymbolAddress((void**)&prt,  g_rt);
    cudaGetSymbolAddress((void**)&prw,  g_rw);

    cudaFuncSetAttribute(flash_mma_k,
                         cudaFuncAttributeMaxDynamicSharedMemorySize, FA_SMEM_BYTES);
    cudaFuncSetAttribute(mma_multi4,
                         cudaFuncAttributeMaxDynamicSharedMemorySize, MM_SMEM_BYTES);
    cudaFuncSetAttribute(mma_gu_routed,
                         cudaFuncAttributeMaxDynamicSharedMemorySize, MM_SMEM_BYTES);
    cudaFuncSetAttribute(mma_down_routed,
                         cudaFuncAttributeMaxDynamicSharedMemorySize, MM_SMEM_BYTES);
    cudaFuncSetAttribute(mma_down_shared,
                         cudaFuncAttributeMaxDynamicSharedMemorySize, MM_SMEM_BYTES);

    // 1) h = rmsnorm(x)
    rmsnorm_k<<<T_, 256>>>(x, attn_nw, ph);

    // 2) fused projections: w_q (16 tiles) + w_dkv (4) + w_kr (1)
    mma_multi4<<<dim3(21, T_/128), 256, MM_SMEM_BYTES>>>(ph, D_,
        w_q,   pq,   H_*QDIM_, 16,
        w_dkv, plat, DL_,      4,
        w_kr,  pkr,  DR_,      1,
        nullptr, nullptr, 0, 0, nullptr);

    // 3) RoPE
    {
        int n = T_*H_*32 + T_*32;
        rope_k<<<(n + 255)/256, 256>>>(pq, pkr);
    }

    // 4) fused k_c + v up-projections
    mma_multi4<<<dim3(16, T_/128), 256, MM_SMEM_BYTES>>>(plat, DL_,
        w_uk, pkc, H_*DH_, 8,
        w_uv, pv,  H_*DH_, 8,
        nullptr, nullptr, 0, 0,
        nullptr, nullptr, 0, 0, nullptr);

    // 5) attention
    flash_mma_k<<<dim3(S_/64, B_*H_), 128, FA_SMEM_BYTES>>>(pq, pkc, pkr, pv, pctx);

    // 6) out = x + ctx @ w_o
    mma_multi4<<<dim3(8, T_/128), 256, MM_SMEM_BYTES>>>(pctx, H_*DH_,
        w_o, out, D_, 8,
        nullptr, nullptr, 0, 0,
        nullptr, nullptr, 0, 0,
        nullptr, nullptr, 0, 0, x);

    // 7) h2 = rmsnorm(out)
    rmsnorm_k<<<T_, 256>>>(out, mlp_nw, ph2);

    // 8) routing
    zero_cnt_k<<<1, 32>>>(pcnt);
    gate_topk_k<<<T_/8, 256>>>(ph2, gate_w, pcnt, pel, prt, prw);

    // 9) shared experts: gate+up (both experts) in one launch
    mma_multi4<<<dim3(16, T_/128), 256, MM_SMEM_BYTES>>>(ph2, D_,
        ws_gate,              pgsh,               DHID_, 4,
        ws_up,                push,               DHID_, 4,
        ws_gate + (size_t)D_*DHID_, pgsh + (size_t)T_*DHID_, DHID_, 4,
        ws_up   + (size_t)D_*DHID_, push + (size_t)T_*DHID_, DHID_, 4,
        nullptr);
    silu_batched_k<<<dim3((T_*DHID_ + 255)/256, NS_), 256>>>(pgsh, push, pgsh, nullptr);
    mma_down_shared<<<dim3(D_/128, T_/128, NS_), 256, MM_SMEM_BYTES>>>(pgsh, ws_down, pysh);

    // 10) routed experts: batched gate+up, silu, down (compact outputs)
    mma_gu_routed<<<dim3(2*DHID_/128, T_/128, NR_), 256, MM_SMEM_BYTES>>>(ph2, wr_gate, wr_up,
                                                           pgb, pub, pel, pcnt);
    silu_batched_k<<<dim3((T_*DHID_ + 255)/256, NR_), 256>>>(pgb, pub, pgb, pcnt);
    mma_down_routed<<<dim3(D_/128, T_/128, NR_), 256, MM_SMEM_BYTES>>>(pgb, wr_down, py, pcnt);

    // 11) deterministic combine
    reduce_k<<<T_, 256>>>(out, pysh, py, prt, prw);
}

// round 14
// speedup vs baseline: 1.0979x; 1.0979x over previous
#include <cuda_runtime.h>
#include <math.h>

#define B_ 2
#define S_ 2048
#define D_ 1024
#define H_ 16
#define DH_ 64
#define DR_ 64
#define DL_ 512
#define DHID_ 512
#define NR_ 8
#define NS_ 2
#define T_ (B_*S_)          // 4096 tokens
#define QDIM_ (DH_+DR_)     // 128

// ---------------- scratch (device globals; no allocation allowed) ----------
__device__ float g_h  [T_*D_];
__device__ float g_q  [T_*H_*QDIM_];
__device__ float g_lat[T_*DL_];
__device__ float g_kc [T_*H_*DH_];
__device__ float g_v  [T_*H_*DH_];
__device__ float g_kr [T_*DR_];
__device__ float g_ctx[T_*H_*DH_];
__device__ float g_h2 [T_*D_];
__device__ int   g_cnt[NR_];
__device__ int   g_elist[NR_*T_];
__device__ int   g_rt  [T_*4];        // per-token (e1,pos1,e2,pos2)
__device__ float g_rw  [T_*2];        // per-token (w1,w2)
// shared experts
__device__ float g_gsh[NS_*T_*DHID_];
__device__ float g_ush[NS_*T_*DHID_];
__device__ float g_ysh[NS_*T_*D_];
// routed experts (compact per-expert regions, stride T_ rows)
__device__ float g_gb [NR_*T_*DHID_];
__device__ float g_ub [NR_*T_*DHID_];
__device__ float g_y  [NR_*T_*D_];

__device__ __forceinline__ unsigned f2tf(float x) {
    unsigned r;
    asm("cvt.rna.tf32.f32 %0, %1;" : "=r"(r) : "f"(x));
    return r;
}

__device__ __forceinline__ void cp16(float* dst, const float* src) {
    unsigned d = (unsigned)__cvta_generic_to_shared(dst);
    asm volatile("cp.async.cg.shared.global [%0], [%1], 16;" :: "r"(d), "l"(src));
}

// ---------------- rmsnorm --------------------------------------------------
__global__ void rmsnorm_k(const float* __restrict__ x, const float* __restrict__ w,
                          float* __restrict__ o) {
    int row = blockIdx.x;
    const float* xr = x + (size_t)row * D_;
    float ss = 0.f;
    float vloc[4];
#pragma unroll
    for (int i = 0; i < 4; i++) { vloc[i] = xr[threadIdx.x + i*256]; ss += vloc[i]*vloc[i]; }
#pragma unroll
    for (int off = 16; off; off >>= 1) ss += __shfl_xor_sync(0xffffffffu, ss, off);
    __shared__ float sm[8];
    __shared__ float invs;
    if ((threadIdx.x & 31) == 0) sm[threadIdx.x >> 5] = ss;
    __syncthreads();
    if (threadIdx.x == 0) {
        float t = 0.f;
#pragma unroll
        for (int i = 0; i < 8; i++) t += sm[i];
        invs = 1.0f / sqrtf(t / (float)D_ + 1e-6f);
    }
    __syncthreads();
    float inv = invs;
    float* orow = o + (size_t)row * D_;
#pragma unroll
    for (int i = 0; i < 4; i++) {
        int d = threadIdx.x + i*256;
        orow[d] = vloc[i] * inv * w[d];
    }
}

// ---------------- tf32 mma core: 128x128x16, 4-stage cp.async (R11) --------
#define STG_ 4
#define SA_STRIDE 20                 // 16 k + 4 pad (banks (20r+cq)%32 distinct)
#define SB_STRIDE 136                // 128 n + 8 pad
#define SA_SZ (128*SA_STRIDE)        // floats per stage (A)
#define SB_SZ (16*SB_STRIDE)         // floats per stage (B)
#define STG_SZ (SA_SZ + SB_SZ)
#define MM_SMEM_BYTES (STG_*STG_SZ*4)   // 75,776 B

// cnt < 0 : dense. cnt >= 0: rows bounded by cnt (clamped loads, guarded writes).
// idx != null: A rows gathered via idx. C rows always compact (= global row).
// Dadd != null: C = Dadd + acc. N may be < 128 (multiple of 8).
__device__ __forceinline__ void mma_core(
        const float* __restrict__ A, const float* __restrict__ Bm,
        float* __restrict__ C, int N, int K, int bx, int by,
        int cnt, const int* __restrict__ idx, const float* __restrict__ Dadd) {
    extern __shared__ float smdyn[];

    int tid = threadIdx.x;
    int warp = tid >> 5, lane = tid & 31;
    int wm = warp & 3;
    int wn = warp >> 2;
    int r  = lane >> 2;
    int cq = lane & 3;

    float acc[2][8][4];
#pragma unroll
    for (int i = 0; i < 2; i++)
#pragma unroll
        for (int j = 0; j < 8; j++)
#pragma unroll
            for (int k = 0; k < 4; k++) acc[i][j][k] = 0.f;

    // A loader: thread -> row ar (0..127), k-offset ak (0 or 8)
    int ar = tid >> 1;
    int ak = (tid & 1) * 8;
    int gRowA = by*128 + ar;
    int rowA;
    if (idx) {
        int rs = (cnt >= 0 && gRowA >= cnt) ? (cnt - 1) : gRowA;
        rowA = idx[rs];
    } else if (cnt >= 0) {
        rowA = (gRowA < cnt) ? gRowA : (cnt - 1);
    } else {
        rowA = gRowA;
    }
    const float* Arow = A + (size_t)rowA * K + ak;
    int aDstOff = ar*SA_STRIDE + ak;

    // B loader: thread -> k-row br (0..15), n-offset bc
    int br = tid >> 4;
    int bc = (tid & 15) * 8;
    int bcc = (bc + 8 <= N) ? bc : (N - 8);     // src clamp for N<128
    const float* Bsrc0 = Bm + (size_t)br * N + (size_t)bx*128 + bcc;
    int bDstOff = SA_SZ + br*SB_STRIDE + bc;

    int ntiles = K >> 4;

    // prologue: stages 0..STG_-2
#pragma unroll
    for (int p = 0; p < STG_-1; p++) {
        float* st = smdyn + p*STG_SZ;
        const float* as = Arow + p*16;
        cp16(st + aDstOff,     as);
        cp16(st + aDstOff + 4, as + 4);
        const float* bs = Bsrc0 + (size_t)p * 16 * N;
        cp16(st + bDstOff,     bs);
        cp16(st + bDstOff + 4, bs + 4);
        asm volatile("cp.async.commit_group;");
    }

    for (int kt = 0; kt < ntiles; kt++) {
        asm volatile("cp.async.wait_group %0;" :: "n"(STG_-2));
        __syncthreads();

        const unsigned* As = (const unsigned*)(smdyn + (kt & (STG_-1))*STG_SZ);
        const unsigned* Bs = As + SA_SZ;

#pragma unroll
        for (int kk = 0; kk < 16; kk += 8) {
            unsigned a[2][4];
#pragma unroll
            for (int i = 0; i < 2; i++) {
                int m0 = (wm*32 + i*16 + r) * SA_STRIDE;
                a[i][0] = As[m0                + kk + cq];
                a[i][1] = As[m0 + 8*SA_STRIDE  + kk + cq];
                a[i][2] = As[m0                + kk + cq + 4];
                a[i][3] = As[m0 + 8*SA_STRIDE  + kk + cq + 4];
            }
#pragma unroll
            for (int j = 0; j < 8; j++) {
                int n0 = wn*64 + j*8 + r;
                unsigned b0 = Bs[(kk+cq  )*SB_STRIDE + n0];
                unsigned b1 = Bs[(kk+cq+4)*SB_STRIDE + n0];
#pragma unroll
                for (int i = 0; i < 2; i++) {
                    asm volatile(
                        "mma.sync.aligned.m16n8k8.row.col.f32.tf32.tf32.f32 "
                        "{%0,%1,%2,%3},{%4,%5,%6,%7},{%8,%9},{%0,%1,%2,%3};"
                        : "+f"(acc[i][j][0]), "+f"(acc[i][j][1]),
                          "+f"(acc[i][j][2]), "+f"(acc[i][j][3])
                        : "r"(a[i][0]), "r"(a[i][1]), "r"(a[i][2]), "r"(a[i][3]),
                          "r"(b0), "r"(b1));
                }
            }
        }

        int kn = kt + STG_ - 1;
        if (kn < ntiles) {
            float* st = smdyn + (kn & (STG_-1))*STG_SZ;
            const float* as = Arow + kn*16;
            cp16(st + aDstOff,     as);
            cp16(st + aDstOff + 4, as + 4);
            const float* bs = Bsrc0 + (size_t)kn * 16 * N;
            cp16(st + bDstOff,     bs);
            cp16(st + bDstOff + 4, bs + 4);
        }
        asm volatile("cp.async.commit_group;");
    }

#pragma unroll
    for (int i = 0; i < 2; i++) {
        int lrow = wm*32 + i*16 + r;
        int gr0 = by*128 + lrow;
        int gr1 = gr0 + 8;
#pragma unroll
        for (int half = 0; half < 2; half++) {
            int gr = half ? gr1 : gr0;
            if (cnt >= 0 && gr >= cnt) continue;
            float* cbase = C + (size_t)gr * N + (size_t)bx*128 + wn*64;
            const float* dbase = Dadd ? (Dadd + (size_t)gr * N + (size_t)bx*128 + wn*64)
                                      : nullptr;
#pragma unroll
            for (int j = 0; j < 8; j++) {
                int ncol = wn*64 + j*8 + cq*2;
                if (bx*128 + ncol >= N && N < 128) continue;  // N<128 guard
                float v0 = acc[i][j][half*2 + 0];
                float v1 = acc[i][j][half*2 + 1];
                float2* p = (float2*)(cbase + j*8 + cq*2);
                if (dbase) {
                    float2 dv = *(const float2*)(dbase + j*8 + cq*2);
                    float2 nv; nv.x = dv.x + v0; nv.y = dv.y + v1;
                    *p = nv;
                } else {
                    float2 nv; nv.x = v0; nv.y = v1;
                    *p = nv;
                }
            }
        }
    }
}

// ---- dense multi-segment (same A, up to 4 (B,C,N) segments along grid.x) --
__global__ __launch_bounds__(256, 2) void mma_multi4(
        const float* __restrict__ A, int K,
        const float* B0, float* C0, int N0, int X0,
        const float* B1, float* C1, int N1, int X1,
        const float* B2, float* C2, int N2, int X2,
        const float* B3, float* C3, int N3, int X3,
        const float* __restrict__ Dadd) {
    int bx = blockIdx.x;
    const float* Bm; float* C; int N;
    if (bx < X0)                { Bm = B0; C = C0; N = N0; }
    else if (bx < X0+X1)        { bx -= X0; Bm = B1; C = C1; N = N1; }
    else if (bx < X0+X1+X2)     { bx -= X0+X1; Bm = B2; C = C2; N = N2; }
    else                        { bx -= X0+X1+X2; Bm = B3; C = C3; N = N3; }
    mma_core(A, Bm, C, N, K, bx, blockIdx.y, -1, nullptr, Dadd);
}

// ---- routed experts: gate+up batched over z=expert, gathered A ------------
__global__ __launch_bounds__(256, 2) void mma_gu_routed(
        const float* __restrict__ h2, const float* __restrict__ wr_gate,
        const float* __restrict__ wr_up, float* __restrict__ gb,
        float* __restrict__ ub, const int* __restrict__ elist,
        const int* __restrict__ cntArr) {
    int e = blockIdx.z;
    int cnt = cntArr[e];
    if ((int)blockIdx.y * 128 >= cnt) return;
    int bx = blockIdx.x;
    const float* Bm; float* C;
    if (bx < DHID_/128) { Bm = wr_gate + (size_t)e*D_*DHID_; C = gb + (size_t)e*T_*DHID_; }
    else { bx -= DHID_/128; Bm = wr_up + (size_t)e*D_*DHID_; C = ub + (size_t)e*T_*DHID_; }
    mma_core(h2, Bm, C, DHID_, D_, bx, blockIdx.y, cnt, elist + e*T_, nullptr);
}

// ---- routed experts: down batched, compact in -> compact out --------------
__global__ __launch_bounds__(256, 2) void mma_down_routed(
        const float* __restrict__ gb, const float* __restrict__ wr_down,
        float* __restrict__ y, const int* __restrict__ cntArr) {
    int e = blockIdx.z;
    int cnt = cntArr[e];
    if ((int)blockIdx.y * 128 >= cnt) return;
    mma_core(gb + (size_t)e*T_*DHID_, wr_down + (size_t)e*DHID_*D_,
             y + (size_t)e*T_*D_, D_, DHID_, blockIdx.x, blockIdx.y,
             cnt, nullptr, nullptr);
}

// ---- shared experts: down batched over z ----------------------------------
__global__ __launch_bounds__(256, 2) void mma_down_shared(
        const float* __restrict__ gsh, const float* __restrict__ ws_down,
        float* __restrict__ ysh) {
    int s = blockIdx.z;
    mma_core(gsh + (size_t)s*T_*DHID_, ws_down + (size_t)s*DHID_*D_,
             ysh + (size_t)s*T_*D_, D_, DHID_, blockIdx.x, blockIdx.y,
             -1, nullptr, nullptr);
}

// ---------------- RoPE (in-place on q tail + k_r) --------------------------
__global__ void rope_k(float* __restrict__ q, float* __restrict__ kr) {
    int p = blockIdx.x * blockDim.x + threadIdx.x;
    const int NQ = T_ * H_ * 32;
    const int NK = T_ * 32;
    if (p < NQ) {
        int i = p & 31;
        int h = (p >> 5) & (H_ - 1);
        int t = p >> 9;
        int s = t & (S_ - 1);
        float inv = powf(10000.0f, -(float)i / 32.0f);
        float sn, c;
        sincosf((float)s * inv, &sn, &c);
        float* base = q + (size_t)t * (H_*QDIM_) + h * QDIM_ + DH_;
        float t1 = base[i], t2 = base[32 + i];
        base[i]      = t1 * c - t2 * sn;
        base[32 + i] = t2 * c + t1 * sn;
    } else if (p < NQ + NK) {
        int p2 = p - NQ;
        int i = p2 & 31;
        int t = p2 >> 5;
        int s = t & (S_ - 1);
        float inv = powf(10000.0f, -(float)i / 32.0f);
        float sn, c;
        sincosf((float)s * inv, &sn, &c);
        float* base = kr + (size_t)t * DR_;
        float t1 = base[i], t2 = base[32 + i];
        base[i]      = t1 * c - t2 * sn;
        base[32 + i] = t2 * c + t1 * sn;
    }
}

// -------- tensor-core flash attention: 128 q-rows/CTA, 8 warps -------------
// Per-warp structure identical to R11 (warp owns 16 q-rows); K/V tiles now
// amortized over 128 q-rows and 2 warps/SMSP hide smem/EX2 latency.
#define FA_SMEM_FLOATS (128*132 + 64*132 + 64*68 + 8*16*68)
#define FA_SMEM_BYTES  (FA_SMEM_FLOATS*4)   // 153,600 B

__global__ __launch_bounds__(256) void flash_mma_k(
        const float* __restrict__ q, const float* __restrict__ kc,
        const float* __restrict__ kr, const float* __restrict__ v,
        float* __restrict__ ctx) {
    extern __shared__ unsigned smbuf[];
    unsigned* Qs = smbuf;                 // [128][132]
    unsigned* Ks = Qs + 128*132;          // [64][132]
    unsigned* Vs = Ks + 64*132;           // [64][68]
    unsigned* Ps = Vs + 64*68;            // [8][16][68]

    int qb = blockIdx.x;
    int bh = blockIdx.y;
    int b = bh >> 4, h = bh & 15;
    int tid = threadIdx.x;
    int warp = tid >> 5, lane = tid & 31;
    int r = lane >> 2, cq = lane & 3;
    size_t tq = (size_t)b*S_ + qb*128;
    unsigned* Pw = Ps + warp*16*68;

    // load Q tile (128 x 128) as tf32: 4096 float4, 256 threads, 16 iters
#pragma unroll
    for (int i = 0; i < 16; i++) {
        int e = i*256 + tid;
        int row = e >> 5, c4 = (e & 31) * 4;
        float4 qv = *(const float4*)&q[(tq+row)*(size_t)(H_*QDIM_) + h*QDIM_ + c4];
        unsigned* dst = &Qs[row*132 + c4];
        dst[0]=f2tf(qv.x); dst[1]=f2tf(qv.y); dst[2]=f2tf(qv.z); dst[3]=f2tf(qv.w);
    }

    float m0 = -1e30f, m1 = -1e30f;
    float l0 = 0.f,  l1 = 0.f;
    float o[8][4];
#pragma unroll
    for (int j = 0; j < 8; j++)
#pragma unroll
        for (int k = 0; k < 4; k++) o[j][k] = 0.f;

    const float scale = 0.088388347648318447f;   // 1/sqrt(128)
    int nkb = 2*qb + 2;

    for (int kb = 0; kb < nkb; kb++) {
        size_t tk = (size_t)b*S_ + kb*64;
        __syncthreads();
        // K tile: kc (cols 0..63) + kr (cols 64..127); 1024 float4 each part /4 iters
#pragma unroll
        for (int i = 0; i < 4; i++) {
            int e = i*256 + tid;
            int row = e >> 4, c4 = (e & 15) * 4;
            float4 kv = *(const float4*)&kc[(tk+row)*(size_t)(H_*DH_) + h*DH_ + c4];
            unsigned* dst = &Ks[row*132 + c4];
            dst[0]=f2tf(kv.x); dst[1]=f2tf(kv.y); dst[2]=f2tf(kv.z); dst[3]=f2tf(kv.w);
        }
#pragma unroll
        for (int i = 0; i < 4; i++) {
            int e = i*256 + tid;
            int row = e >> 4, c4 = (e & 15) * 4;
            float4 kv = *(const float4*)&kr[(tk+row)*(size_t)DR_ + c4];
            unsigned* dst = &Ks[row*132 + 64 + c4];
            dst[0]=f2tf(kv.x); dst[1]=f2tf(kv.y); dst[2]=f2tf(kv.z); dst[3]=f2tf(kv.w);
        }
#pragma unroll
        for (int i = 0; i < 4; i++) {
            int e = i*256 + tid;
            int row = e >> 4, c4 = (e & 15) * 4;
            float4 vv = *(const float4*)&v[(tk+row)*(size_t)(H_*DH_) + h*DH_ + c4];
            unsigned* dst = &Vs[row*68 + c4];
            dst[0]=f2tf(vv.x); dst[1]=f2tf(vv.y); dst[2]=f2tf(vv.z); dst[3]=f2tf(vv.w);
        }
        __syncthreads();

        float s[8][4];
#pragma unroll
        for (int j = 0; j < 8; j++)
#pragma unroll
            for (int k = 0; k < 4; k++) s[j][k] = 0.f;

#pragma unroll
        for (int kk = 0; kk < 128; kk += 8) {
            int m0r = (warp*16 + r)*132;
            unsigned a0 = Qs[m0r + kk + cq];
            unsigned a1 = Qs[m0r + 8*132 + kk + cq];
            unsigned a2 = Qs[m0r + kk + cq + 4];
            unsigned a3 = Qs[m0r + 8*132 + kk + cq + 4];
#pragma unroll
            for (int j = 0; j < 8; j++) {
                unsigned b0 = Ks[(j*8 + r)*132 + kk + cq];
                unsigned b1 = Ks[(j*8 + r)*132 + kk + cq + 4];
                asm volatile(
                    "mma.sync.aligned.m16n8k8.row.col.f32.tf32.tf32.f32 "
                    "{%0,%1,%2,%3},{%4,%5,%6,%7},{%8,%9},{%0,%1,%2,%3};"
                    : "+f"(s[j][0]), "+f"(s[j][1]), "+f"(s[j][2]), "+f"(s[j][3])
                    : "r"(a0), "r"(a1), "r"(a2), "r"(a3), "r"(b0), "r"(b1));
            }
        }

        // scale + causal mask (last two key blocks may cross the diagonal)
        bool maybe_mask = (kb >= 2*qb);
        int qg0 = qb*128 + warp*16 + r;      // global q row for c0,c1
        int qg1 = qg0 + 8;
        int kg  = kb*64;
#pragma unroll
        for (int j = 0; j < 8; j++) {
            int c0 = kg + j*8 + cq*2, c1 = c0 + 1;
            s[j][0] *= scale; s[j][1] *= scale;
            s[j][2] *= scale; s[j][3] *= scale;
            if (maybe_mask) {
                if (c0 > qg0) s[j][0] = -1e9f;
                if (c1 > qg0) s[j][1] = -1e9f;
                if (c0 > qg1) s[j][2] = -1e9f;
                if (c1 > qg1) s[j][3] = -1e9f;
            }
        }

        float mt0 = -1e30f, mt1 = -1e30f;
#pragma unroll
        for (int j = 0; j < 8; j++) {
            mt0 = fmaxf(mt0, fmaxf(s[j][0], s[j][1]));
            mt1 = fmaxf(mt1, fmaxf(s[j][2], s[j][3]));
        }
        mt0 = fmaxf(mt0, __shfl_xor_sync(0xffffffffu, mt0, 1));
        mt0 = fmaxf(mt0, __shfl_xor_sync(0xffffffffu, mt0, 2));
        mt1 = fmaxf(mt1, __shfl_xor_sync(0xffffffffu, mt1, 1));
        mt1 = fmaxf(mt1, __shfl_xor_sync(0xffffffffu, mt1, 2));

        float mn0 = fmaxf(m0, mt0), mn1 = fmaxf(m1, mt1);
        float al0 = __expf(m0 - mn0), al1 = __expf(m1 - mn1);
        m0 = mn0; m1 = mn1;

        float ps0 = 0.f, ps1 = 0.f;
#pragma unroll
        for (int j = 0; j < 8; j++) {
            s[j][0] = __expf(s[j][0] - mn0);
            s[j][1] = __expf(s[j][1] - mn0);
            s[j][2] = __expf(s[j][2] - mn1);
            s[j][3] = __expf(s[j][3] - mn1);
            ps0 += s[j][0] + s[j][1];
            ps1 += s[j][2] + s[j][3];
        }
        ps0 += __shfl_xor_sync(0xffffffffu, ps0, 1);
        ps0 += __shfl_xor_sync(0xffffffffu, ps0, 2);
        ps1 += __shfl_xor_sync(0xffffffffu, ps1, 1);
        ps1 += __shfl_xor_sync(0xffffffffu, ps1, 2);
        l0 = l0 * al0 + ps0;
        l1 = l1 * al1 + ps1;

#pragma unroll
        for (int j = 0; j < 8; j++) {
            o[j][0] *= al0; o[j][1] *= al0;
            o[j][2] *= al1; o[j][3] *= al1;
        }

        // P -> smem (tf32), warp-local
#pragma unroll
        for (int j = 0; j < 8; j++) {
            int c0 = j*8 + cq*2;
            Pw[r*68 + c0]       = f2tf(s[j][0]);
            Pw[r*68 + c0 + 1]   = f2tf(s[j][1]);
            Pw[(r+8)*68 + c0]     = f2tf(s[j][2]);
            Pw[(r+8)*68 + c0 + 1] = f2tf(s[j][3]);
        }
        __syncwarp();

        // O += P @ V
#pragma unroll
        for (int kk = 0; kk < 64; kk += 8) {
            unsigned a0 = Pw[r*68 + kk + cq];
            unsigned a1 = Pw[(r+8)*68 + kk + cq];
            unsigned a2 = Pw[r*68 + kk + cq + 4];
            unsigned a3 = Pw[(r+8)*68 + kk + cq + 4];
#pragma unroll
            for (int j = 0; j < 8; j++) {
                unsigned b0 = Vs[(kk+cq)*68 + j*8 + r];
                unsigned b1 = Vs[(kk+cq+4)*68 + j*8 + r];
                asm volatile(
                    "mma.sync.aligned.m16n8k8.row.col.f32.tf32.tf32.f32 "
                    "{%0,%1,%2,%3},{%4,%5,%6,%7},{%8,%9},{%0,%1,%2,%3};"
                    : "+f"(o[j][0]), "+f"(o[j][1]), "+f"(o[j][2]), "+f"(o[j][3])
                    : "r"(a0), "r"(a1), "r"(a2), "r"(a3), "r"(b0), "r"(b1));
            }
        }
        __syncwarp();
    }

    float inv0 = 1.f / l0, inv1 = 1.f / l1;
    size_t row0 = (tq + warp*16 + r) * (size_t)(H_*DH_) + h*DH_;
    size_t row1 = row0 + (size_t)8 * (H_*DH_);
#pragma unroll
    for (int j = 0; j < 8; j++) {
        int c0 = j*8 + cq*2;
        float2 v0; v0.x = o[j][0]*inv0; v0.y = o[j][1]*inv0;
        float2 v1; v1.x = o[j][2]*inv1; v1.y = o[j][3]*inv1;
        *(float2*)&ctx[row0 + c0] = v0;
        *(float2*)&ctx[row1 + c0] = v1;
    }
}

// ---------------- misc elementwise ----------------------------------------
__global__ void zero_cnt_k(int* c) {
    if (threadIdx.x < NR_) c[threadIdx.x] = 0;
}

// z = blockIdx.y selects slice; cntArr null => dense (cnt = T_)
__global__ void silu_batched_k(const float* __restrict__ g, const float* __restrict__ u,
                               float* __restrict__ o, const int* __restrict__ cntArr) {
    int z = blockIdx.y;
    int cnt = cntArr ? cntArr[z] : T_;
    long i = (long)blockIdx.x * blockDim.x + threadIdx.x;
    if (i >= (long)cnt * DHID_) return;
    size_t base = (size_t)z * T_ * DHID_;
    float gv = g[base + i], uv = u[base + i];
    o[base + i] = (gv / (1.f + __expf(-gv))) * uv;
}

// ---------------- gating: logits + softmax + top2 + routing ----------------
__global__ void gate_topk_k(const float* __restrict__ h2, const float* __restrict__ gw,
                            int* __restrict__ cnt, int* __restrict__ elist,
                            int* __restrict__ rt, float* __restrict__ rw) {
    int t = blockIdx.x * 8 + (threadIdx.x >> 5);
    int lane = threadIdx.x & 31;
    if (t >= T_) return;
    float acc[NR_];
#pragma unroll
    for (int e = 0; e < NR_; e++) acc[e] = 0.f;
    const float* hr = h2 + (size_t)t * D_;
    for (int d = lane; d < D_; d += 32) {
        float xv = hr[d];
        const float* g = gw + (size_t)d * NR_;
#pragma unroll
        for (int e = 0; e < NR_; e++) acc[e] += xv * g[e];
    }
#pragma unroll
    for (int e = 0; e < NR_; e++)
#pragma unroll
        for (int off = 16; off; off >>= 1)
            acc[e] += __shfl_xor_sync(0xffffffffu, acc[e], off);
    if (lane == 0) {
        int i1 = 0;
#pragma unroll
        for (int e = 1; e < NR_; e++) if (acc[e] > acc[i1]) i1 = e;
        int i2 = (i1 == 0) ? 1 : 0;
#pragma unroll
        for (int e = 0; e < NR_; e++) {
            if (e == i1 || e == i2) continue;
            if (acc[e] > acc[i2]) i2 = e;
        }
        float p2 = __expf(acc[i2] - acc[i1]);
        float inv = 1.f / (1.f + p2);
        float w1 = inv, w2 = p2 * inv;
        int pos1 = atomicAdd(&cnt[i1], 1);
        elist[i1*T_ + pos1] = t;
        int pos2 = atomicAdd(&cnt[i2], 1);
        elist[i2*T_ + pos2] = t;
        rt[t*4+0] = i1; rt[t*4+1] = pos1;
        rt[t*4+2] = i2; rt[t*4+3] = pos2;
        rw[t*2+0] = w1; rw[t*2+1] = w2;
    }
}

// ---------------- final reduce: out += shared + routed ---------------------
__global__ void reduce_k(float* __restrict__ out, const float* __restrict__ ysh,
                         const float* __restrict__ y, const int* __restrict__ rt,
                         const float* __restrict__ rw) {
    int t = blockIdx.x;
    int tid = threadIdx.x;
    int e1 = rt[t*4+0], p1 = rt[t*4+1];
    int e2 = rt[t*4+2], p2 = rt[t*4+3];
    float w1 = rw[t*2+0], w2 = rw[t*2+1];
    const float4* s0 = (const float4*)(ysh + (size_t)t * D_);
    const float4* s1 = (const float4*)(ysh + ((size_t)T_ + t) * D_);
    const float4* y1 = (const float4*)(y + ((size_t)e1*T_ + p1) * D_);
    const float4* y2 = (const float4*)(y + ((size_t)e2*T_ + p2) * D_);
    float4* op = (float4*)(out + (size_t)t * D_);
    for (int d = tid; d < D_/4; d += blockDim.x) {
        float4 o = op[d];
        float4 a = s0[d], b = s1[d], c = y1[d], e = y2[d];
        o.x += a.x + b.x + w1*c.x + w2*e.x;
        o.y += a.y + b.y + w1*c.y + w2*e.y;
        o.z += a.z + b.z + w1*c.z + w2*e.z;
        o.w += a.w + b.w + w1*c.w + w2*e.w;
        op[d] = o;
    }
}

// ---------------- launch ---------------------------------------------------
extern "C" void kernel_launch(void* const* d_in, const int* in_sizes, int n_in,
                              void* d_out, int out_size) {
    const float* x         = (const float*)d_in[0];
    const float* w_q       = (const float*)d_in[2];
    const float* w_dkv     = (const float*)d_in[3];
    const float* w_uk      = (const float*)d_in[4];
    const float* w_uv      = (const float*)d_in[5];
    const float* w_kr      = (const float*)d_in[6];
    const float* w_o       = (const float*)d_in[7];
    const float* attn_nw   = (const float*)d_in[8];
    const float* mlp_nw    = (const float*)d_in[9];
    const float* gate_w    = (const float*)d_in[10];
    const float* wr_gate   = (const float*)d_in[11];
    const float* wr_up     = (const float*)d_in[12];
    const float* wr_down   = (const float*)d_in[13];
    const float* ws_gate   = (const float*)d_in[14];
    const float* ws_up     = (const float*)d_in[15];
    const float* ws_down   = (const float*)d_in[16];
    float* out = (float*)d_out;

    float *ph, *pq, *plat, *pkc, *pv, *pkr, *pctx, *ph2;
    float *pgsh, *push, *pysh, *pgb, *pub, *py, *prw;
    int *pcnt, *pel, *prt;
    cudaGetSymbolAddress((void**)&ph,   g_h);
    cudaGetSymbolAddress((void**)&pq,   g_q);
    cudaGetSymbolAddress((void**)&plat, g_lat);
    cudaGetSymbolAddress((void**)&pkc,  g_kc);
    cudaGetSymbolAddress((void**)&pv,   g_v);
    cudaGetSymbolAddress((void**)&pkr,  g_kr);
    cudaGetSymbolAddress((void**)&pctx, g_ctx);
    cudaGetSymbolAddress((void**)&ph2,  g_h2);
    cudaGetSymbolAddress((void**)&pgsh, g_gsh);
    cudaGetSymbolAddress((void**)&push, g_ush);
    cudaGetSymbolAddress((void**)&pysh, g_ysh);
    cudaGetSymbolAddress((void**)&pgb,  g_gb);
    cudaGetSymbolAddress((void**)&pub,  g_ub);
    cudaGetSymbolAddress((void**)&py,   g_y);
    cudaGetSymbolAddress((void**)&pcnt, g_cnt);
    cudaGetSymbolAddress((void**)&pel,  g_elist);
    cudaGetSymbolAddress((void**)&prt,  g_rt);
    cudaGetSymbolAddress((void**)&prw,  g_rw);

    cudaFuncSetAttribute(flash_mma_k,
                         cudaFuncAttributeMaxDynamicSharedMemorySize, FA_SMEM_BYTES);
    cudaFuncSetAttribute(mma_multi4,
                         cudaFuncAttributeMaxDynamicSharedMemorySize, MM_SMEM_BYTES);
    cudaFuncSetAttribute(mma_gu_routed,
                         cudaFuncAttributeMaxDynamicSharedMemorySize, MM_SMEM_BYTES);
    cudaFuncSetAttribute(mma_down_routed,
                         cudaFuncAttributeMaxDynamicSharedMemorySize, MM_SMEM_BYTES);
    cudaFuncSetAttribute(mma_down_shared,
                         cudaFuncAttributeMaxDynamicSharedMemorySize, MM_SMEM_BYTES);

    // 1) h = rmsnorm(x)
    rmsnorm_k<<<T_, 256>>>(x, attn_nw, ph);

    // 2) fused projections: w_q (16 tiles) + w_dkv (4) + w_kr (1)
    mma_multi4<<<dim3(21, T_/128), 256, MM_SMEM_BYTES>>>(ph, D_,
        w_q,   pq,   H_*QDIM_, 16,
        w_dkv, plat, DL_,      4,
        w_kr,  pkr,  DR_,      1,
        nullptr, nullptr, 0, 0, nullptr);

    // 3) RoPE
    {
        int n = T_*H_*32 + T_*32;
        rope_k<<<(n + 255)/256, 256>>>(pq, pkr);
    }

    // 4) fused k_c + v up-projections
    mma_multi4<<<dim3(16, T_/128), 256, MM_SMEM_BYTES>>>(plat, DL_,
        w_uk, pkc, H_*DH_, 8,
        w_uv, pv,  H_*DH_, 8,
        nullptr, nullptr, 0, 0,
        nullptr, nullptr, 0, 0, nullptr);

    // 5) attention (128 q-rows/CTA, 8 warps)
    flash_mma_k<<<dim3(S_/128, B_*H_), 256, FA_SMEM_BYTES>>>(pq, pkc, pkr, pv, pctx);

    // 6) out = x + ctx @ w_o
    mma_multi4<<<dim3(8, T_/128), 256, MM_SMEM_BYTES>>>(pctx, H_*DH_,
        w_o, out, D_, 8,
        nullptr, nullptr, 0, 0,
        nullptr, nullptr, 0, 0,
        nullptr, nullptr, 0, 0, x);

    // 7) h2 = rmsnorm(out)
    rmsnorm_k<<<T_, 256>>>(out, mlp_nw, ph2);

    // 8) routing
    zero_cnt_k<<<1, 32>>>(pcnt);
    gate_topk_k<<<T_/8, 256>>>(ph2, gate_w, pcnt, pel, prt, prw);

    // 9) shared experts: gate+up (both experts) in one launch
    mma_multi4<<<dim3(16, T_/128), 256, MM_SMEM_BYTES>>>(ph2, D_,
        ws_gate,              pgsh,               DHID_, 4,
        ws_up,                push,               DHID_, 4,
        ws_gate + (size_t)D_*DHID_, pgsh + (size_t)T_*DHID_, DHID_, 4,
        ws_up   + (size_t)D_*DHID_, push + (size_t)T_*DHID_, DHID_, 4,
        nullptr);
    silu_batched_k<<<dim3((T_*DHID_ + 255)/256, NS_), 256>>>(pgsh, push, pgsh, nullptr);
    mma_down_shared<<<dim3(D_/128, T_/128, NS_), 256, MM_SMEM_BYTES>>>(pgsh, ws_down, pysh);

    // 10) routed experts: batched gate+up, silu, down (compact outputs)
    mma_gu_routed<<<dim3(2*DHID_/128, T_/128, NR_), 256, MM_SMEM_BYTES>>>(ph2, wr_gate, wr_up,
                                                           pgb, pub, pel, pcnt);
    silu_batched_k<<<dim3((T_*DHID_ + 255)/256, NR_), 256>>>(pgb, pub, pgb, pcnt);
    mma_down_routed<<<dim3(D_/128, T_/128, NR_), 256, MM_SMEM_BYTES>>>(pgb, wr_down, py, pcnt);

    // 11) deterministic combine
    reduce_k<<<T_, 256>>>(out, pysh, py, prt, prw);
}

// round 16
// speedup vs baseline: 1.1811x; 1.0758x over previous
#include <cuda_runtime.h>
#include <math.h>

#define B_ 2
#define S_ 2048
#define D_ 1024
#define H_ 16
#define DH_ 64
#define DR_ 64
#define DL_ 512
#define DHID_ 512
#define NR_ 8
#define NS_ 2
#define NE_ (NR_+NS_)       // 10 expert slices (8 routed + 2 shared)
#define T_ (B_*S_)          // 4096 tokens
#define QDIM_ (DH_+DR_)     // 128

// ---------------- scratch (device globals; no allocation allowed) ----------
__device__ float g_h  [T_*D_];
__device__ float g_q  [T_*H_*QDIM_];
__device__ float g_lat[T_*DL_];
__device__ float g_kc [T_*H_*DH_];
__device__ float g_v  [T_*H_*DH_];
__device__ float g_kr [T_*DR_];
__device__ float g_ctx[T_*H_*DH_];
__device__ float g_h2 [T_*D_];
__device__ int   g_cnt[NR_];
__device__ int   g_elist[NR_*T_];
__device__ int   g_rt  [T_*4];        // per-token (e1,pos1,e2,pos2)
__device__ float g_rw  [T_*2];        // per-token (w1,w2)
// unified expert buffers: slices 0..7 routed (compact rows), 8..9 shared (dense)
__device__ float g_gb [NE_*T_*DHID_];
__device__ float g_ub [NE_*T_*DHID_];
__device__ float g_y  [NE_*T_*D_];

__device__ __forceinline__ unsigned f2tf(float x) {
    unsigned r;
    asm("cvt.rna.tf32.f32 %0, %1;" : "=r"(r) : "f"(x));
    return r;
}

__device__ __forceinline__ void cp16(float* dst, const float* src) {
    unsigned d = (unsigned)__cvta_generic_to_shared(dst);
    asm volatile("cp.async.cg.shared.global [%0], [%1], 16;" :: "r"(d), "l"(src));
}

// ---------------- rmsnorm --------------------------------------------------
__global__ void rmsnorm_k(const float* __restrict__ x, const float* __restrict__ w,
                          float* __restrict__ o) {
    int row = blockIdx.x;
    const float* xr = x + (size_t)row * D_;
    float ss = 0.f;
    float vloc[4];
#pragma unroll
    for (int i = 0; i < 4; i++) { vloc[i] = xr[threadIdx.x + i*256]; ss += vloc[i]*vloc[i]; }
#pragma unroll
    for (int off = 16; off; off >>= 1) ss += __shfl_xor_sync(0xffffffffu, ss, off);
    __shared__ float sm[8];
    __shared__ float invs;
    if ((threadIdx.x & 31) == 0) sm[threadIdx.x >> 5] = ss;
    __syncthreads();
    if (threadIdx.x == 0) {
        float t = 0.f;
#pragma unroll
        for (int i = 0; i < 8; i++) t += sm[i];
        invs = 1.0f / sqrtf(t / (float)D_ + 1e-6f);
    }
    __syncthreads();
    float inv = invs;
    float* orow = o + (size_t)row * D_;
#pragma unroll
    for (int i = 0; i < 4; i++) {
        int d = threadIdx.x + i*256;
        orow[d] = vloc[i] * inv * w[d];
    }
}

// ---------------- tf32 mma core: 128x128x16, 4-stage cp.async (R11) --------
#define STG_ 4
#define SA_STRIDE 20                 // 16 k + 4 pad
#define SB_STRIDE 136                // 128 n + 8 pad
#define SA_SZ (128*SA_STRIDE)
#define SB_SZ (16*SB_STRIDE)
#define STG_SZ (SA_SZ + SB_SZ)
#define MM_SMEM_BYTES (STG_*STG_SZ*4)   // 75,776 B

__device__ __forceinline__ void mma_core(
        const float* __restrict__ A, const float* __restrict__ Bm,
        float* __restrict__ C, int N, int K, int bx, int by,
        int cnt, const int* __restrict__ idx, const float* __restrict__ Dadd) {
    extern __shared__ float smdyn[];

    int tid = threadIdx.x;
    int warp = tid >> 5, lane = tid & 31;
    int wm = warp & 3;
    int wn = warp >> 2;
    int r  = lane >> 2;
    int cq = lane & 3;

    float acc[2][8][4];
#pragma unroll
    for (int i = 0; i < 2; i++)
#pragma unroll
        for (int j = 0; j < 8; j++)
#pragma unroll
            for (int k = 0; k < 4; k++) acc[i][j][k] = 0.f;

    int ar = tid >> 1;
    int ak = (tid & 1) * 8;
    int gRowA = by*128 + ar;
    int rowA;
    if (idx) {
        int rs = (cnt >= 0 && gRowA >= cnt) ? (cnt - 1) : gRowA;
        rowA = idx[rs];
    } else if (cnt >= 0) {
        rowA = (gRowA < cnt) ? gRowA : (cnt - 1);
    } else {
        rowA = gRowA;
    }
    const float* Arow = A + (size_t)rowA * K + ak;
    int aDstOff = ar*SA_STRIDE + ak;

    int br = tid >> 4;
    int bc = (tid & 15) * 8;
    int bcc = (bc + 8 <= N) ? bc : (N - 8);
    const float* Bsrc0 = Bm + (size_t)br * N + (size_t)bx*128 + bcc;
    int bDstOff = SA_SZ + br*SB_STRIDE + bc;

    int ntiles = K >> 4;

#pragma unroll
    for (int p = 0; p < STG_-1; p++) {
        float* st = smdyn + p*STG_SZ;
        const float* as = Arow + p*16;
        cp16(st + aDstOff,     as);
        cp16(st + aDstOff + 4, as + 4);
        const float* bs = Bsrc0 + (size_t)p * 16 * N;
        cp16(st + bDstOff,     bs);
        cp16(st + bDstOff + 4, bs + 4);
        asm volatile("cp.async.commit_group;");
    }

    for (int kt = 0; kt < ntiles; kt++) {
        asm volatile("cp.async.wait_group %0;" :: "n"(STG_-2));
        __syncthreads();

        const unsigned* As = (const unsigned*)(smdyn + (kt & (STG_-1))*STG_SZ);
        const unsigned* Bs = As + SA_SZ;

#pragma unroll
        for (int kk = 0; kk < 16; kk += 8) {
            unsigned a[2][4];
#pragma unroll
            for (int i = 0; i < 2; i++) {
                int m0 = (wm*32 + i*16 + r) * SA_STRIDE;
                a[i][0] = As[m0                + kk + cq];
                a[i][1] = As[m0 + 8*SA_STRIDE  + kk + cq];
                a[i][2] = As[m0                + kk + cq + 4];
                a[i][3] = As[m0 + 8*SA_STRIDE  + kk + cq + 4];
            }
#pragma unroll
            for (int j = 0; j < 8; j++) {
                int n0 = wn*64 + j*8 + r;
                unsigned b0 = Bs[(kk+cq  )*SB_STRIDE + n0];
                unsigned b1 = Bs[(kk+cq+4)*SB_STRIDE + n0];
#pragma unroll
                for (int i = 0; i < 2; i++) {
                    asm volatile(
                        "mma.sync.aligned.m16n8k8.row.col.f32.tf32.tf32.f32 "
                        "{%0,%1,%2,%3},{%4,%5,%6,%7},{%8,%9},{%0,%1,%2,%3};"
                        : "+f"(acc[i][j][0]), "+f"(acc[i][j][1]),
                          "+f"(acc[i][j][2]), "+f"(acc[i][j][3])
                        : "r"(a[i][0]), "r"(a[i][1]), "r"(a[i][2]), "r"(a[i][3]),
                          "r"(b0), "r"(b1));
                }
            }
        }

        int kn = kt + STG_ - 1;
        if (kn < ntiles) {
            float* st = smdyn + (kn & (STG_-1))*STG_SZ;
            const float* as = Arow + kn*16;
            cp16(st + aDstOff,     as);
            cp16(st + aDstOff + 4, as + 4);
            const float* bs = Bsrc0 + (size_t)kn * 16 * N;
            cp16(st + bDstOff,     bs);
            cp16(st + bDstOff + 4, bs + 4);
        }
        asm volatile("cp.async.commit_group;");
    }

#pragma unroll
    for (int i = 0; i < 2; i++) {
        int lrow = wm*32 + i*16 + r;
        int gr0 = by*128 + lrow;
        int gr1 = gr0 + 8;
#pragma unroll
        for (int half = 0; half < 2; half++) {
            int gr = half ? gr1 : gr0;
            if (cnt >= 0 && gr >= cnt) continue;
            float* cbase = C + (size_t)gr * N + (size_t)bx*128 + wn*64;
            const float* dbase = Dadd ? (Dadd + (size_t)gr * N + (size_t)bx*128 + wn*64)
                                      : nullptr;
#pragma unroll
            for (int j = 0; j < 8; j++) {
                int ncol = wn*64 + j*8 + cq*2;
                if (bx*128 + ncol >= N && N < 128) continue;
                float v0 = acc[i][j][half*2 + 0];
                float v1 = acc[i][j][half*2 + 1];
                float2* p = (float2*)(cbase + j*8 + cq*2);
                if (dbase) {
                    float2 dv = *(const float2*)(dbase + j*8 + cq*2);
                    float2 nv; nv.x = dv.x + v0; nv.y = dv.y + v1;
                    *p = nv;
                } else {
                    float2 nv; nv.x = v0; nv.y = v1;
                    *p = nv;
                }
            }
        }
    }
}

// ---- dense multi-segment (same A, up to 4 (B,C,N) segments along grid.x) --
__global__ __launch_bounds__(256, 2) void mma_multi4(
        const float* __restrict__ A, int K,
        const float* B0, float* C0, int N0, int X0,
        const float* B1, float* C1, int N1, int X1,
        const float* B2, float* C2, int N2, int X2,
        const float* B3, float* C3, int N3, int X3,
        const float* __restrict__ Dadd) {
    int bx = blockIdx.x;
    const float* Bm; float* C; int N;
    if (bx < X0)                { Bm = B0; C = C0; N = N0; }
    else if (bx < X0+X1)        { bx -= X0; Bm = B1; C = C1; N = N1; }
    else if (bx < X0+X1+X2)     { bx -= X0+X1; Bm = B2; C = C2; N = N2; }
    else                        { bx -= X0+X1+X2; Bm = B3; C = C3; N = N3; }
    mma_core(A, Bm, C, N, K, bx, blockIdx.y, -1, nullptr, Dadd);
}

// ---- unified experts: gate+up, z = slice (0..7 routed gathered, 8..9 shared dense)
__global__ __launch_bounds__(256, 2) void mma_gu_all(
        const float* __restrict__ h2,
        const float* __restrict__ wr_gate, const float* __restrict__ wr_up,
        const float* __restrict__ ws_gate, const float* __restrict__ ws_up,
        float* __restrict__ gb, float* __restrict__ ub,
        const int* __restrict__ elist, const int* __restrict__ cntArr) {
    int z = blockIdx.z;
    int cnt = -1;
    const int* idx = nullptr;
    const float* Wg; const float* Wu;
    if (z < NR_) {
        cnt = cntArr[z];
        if ((int)blockIdx.y * 128 >= cnt) return;
        idx = elist + z*T_;
        Wg = wr_gate + (size_t)z*D_*DHID_;
        Wu = wr_up   + (size_t)z*D_*DHID_;
    } else {
        Wg = ws_gate + (size_t)(z-NR_)*D_*DHID_;
        Wu = ws_up   + (size_t)(z-NR_)*D_*DHID_;
    }
    int bx = blockIdx.x;
    const float* Bm; float* C;
    if (bx < DHID_/128) { Bm = Wg; C = gb + (size_t)z*T_*DHID_; }
    else { bx -= DHID_/128; Bm = Wu; C = ub + (size_t)z*T_*DHID_; }
    mma_core(h2, Bm, C, DHID_, D_, bx, blockIdx.y, cnt, idx, nullptr);
}

// ---- unified experts: down, compact/dense in -> same out slice ------------
__global__ __launch_bounds__(256, 2) void mma_down_all(
        const float* __restrict__ gb,
        const float* __restrict__ wr_down, const float* __restrict__ ws_down,
        float* __restrict__ y, const int* __restrict__ cntArr) {
    int z = blockIdx.z;
    int cnt = -1;
    const float* Wd;
    if (z < NR_) {
        cnt = cntArr[z];
        if ((int)blockIdx.y * 128 >= cnt) return;
        Wd = wr_down + (size_t)z*DHID_*D_;
    } else {
        Wd = ws_down + (size_t)(z-NR_)*DHID_*D_;
    }
    mma_core(gb + (size_t)z*T_*DHID_, Wd, y + (size_t)z*T_*D_,
             D_, DHID_, blockIdx.x, blockIdx.y, cnt, nullptr, nullptr);
}

// ---------------- RoPE (in-place on q tail + k_r) --------------------------
__global__ void rope_k(float* __restrict__ q, float* __restrict__ kr) {
    int p = blockIdx.x * blockDim.x + threadIdx.x;
    const int NQ = T_ * H_ * 32;
    const int NK = T_ * 32;
    if (p < NQ) {
        int i = p & 31;
        int h = (p >> 5) & (H_ - 1);
        int t = p >> 9;
        int s = t & (S_ - 1);
        float inv = powf(10000.0f, -(float)i / 32.0f);
        float sn, c;
        sincosf((float)s * inv, &sn, &c);
        float* base = q + (size_t)t * (H_*QDIM_) + h * QDIM_ + DH_;
        float t1 = base[i], t2 = base[32 + i];
        base[i]      = t1 * c - t2 * sn;
        base[32 + i] = t2 * c + t1 * sn;
    } else if (p < NQ + NK) {
        int p2 = p - NQ;
        int i = p2 & 31;
        int t = p2 >> 5;
        int s = t & (S_ - 1);
        float inv = powf(10000.0f, -(float)i / 32.0f);
        float sn, c;
        sincosf((float)s * inv, &sn, &c);
        float* base = kr + (size_t)t * DR_;
        float t1 = base[i], t2 = base[32 + i];
        base[i]      = t1 * c - t2 * sn;
        base[32 + i] = t2 * c + t1 * sn;
    }
}

// ------- tensor-core flash attention (R11: 64 q-rows/CTA, 4 warps) ---------
#define FA_SMEM_FLOATS (64*132 + 64*132 + 64*68 + 4*16*68)
#define FA_SMEM_BYTES  (FA_SMEM_FLOATS*4)

__global__ __launch_bounds__(128) void flash_mma_k(
        const float* __restrict__ q, const float* __restrict__ kc,
        const float* __restrict__ kr, const float* __restrict__ v,
        float* __restrict__ ctx) {
    extern __shared__ unsigned smbuf[];
    unsigned* Qs = smbuf;                 // [64][132]
    unsigned* Ks = Qs + 64*132;           // [64][132]
    unsigned* Vs = Ks + 64*132;           // [64][68]
    unsigned* Ps = Vs + 64*68;            // [4][16][68]

    int qb = blockIdx.x;
    int bh = blockIdx.y;
    int b = bh >> 4, h = bh & 15;
    int tid = threadIdx.x;
    int warp = tid >> 5, lane = tid & 31;
    int r = lane >> 2, cq = lane & 3;
    size_t tq = (size_t)b*S_ + qb*64;
    unsigned* Pw = Ps + warp*16*68;

#pragma unroll
    for (int i = 0; i < 16; i++) {
        int e = i*128 + tid;
        int row = e >> 5, c4 = (e & 31) * 4;
        float4 qv = *(const float4*)&q[(tq+row)*(size_t)(H_*QDIM_) + h*QDIM_ + c4];
        unsigned* dst = &Qs[row*132 + c4];
        dst[0]=f2tf(qv.x); dst[1]=f2tf(qv.y); dst[2]=f2tf(qv.z); dst[3]=f2tf(qv.w);
    }

    float m0 = -1e30f, m1 = -1e30f;
    float l0 = 0.f,  l1 = 0.f;
    float o[8][4];
#pragma unroll
    for (int j = 0; j < 8; j++)
#pragma unroll
        for (int k = 0; k < 4; k++) o[j][k] = 0.f;

    const float scale = 0.088388347648318447f;   // 1/sqrt(128)
    int nkb = qb + 1;

    for (int kb = 0; kb < nkb; kb++) {
        size_t tk = (size_t)b*S_ + kb*64;
        __syncthreads();
#pragma unroll
        for (int i = 0; i < 8; i++) {
            int e = i*128 + tid;
            int row = e >> 4, c4 = (e & 15) * 4;
            float4 kv = *(const float4*)&kc[(tk+row)*(size_t)(H_*DH_) + h*DH_ + c4];
            unsigned* dst = &Ks[row*132 + c4];
            dst[0]=f2tf(kv.x); dst[1]=f2tf(kv.y); dst[2]=f2tf(kv.z); dst[3]=f2tf(kv.w);
        }
#pragma unroll
        for (int i = 0; i < 8; i++) {
            int e = i*128 + tid;
            int row = e >> 4, c4 = (e & 15) * 4;
            float4 kv = *(const float4*)&kr[(tk+row)*(size_t)DR_ + c4];
            unsigned* dst = &Ks[row*132 + 64 + c4];
            dst[0]=f2tf(kv.x); dst[1]=f2tf(kv.y); dst[2]=f2tf(kv.z); dst[3]=f2tf(kv.w);
        }
#pragma unroll
        for (int i = 0; i < 8; i++) {
            int e = i*128 + tid;
            int row = e >> 4, c4 = (e & 15) * 4;
            float4 vv = *(const float4*)&v[(tk+row)*(size_t)(H_*DH_) + h*DH_ + c4];
            unsigned* dst = &Vs[row*68 + c4];
            dst[0]=f2tf(vv.x); dst[1]=f2tf(vv.y); dst[2]=f2tf(vv.z); dst[3]=f2tf(vv.w);
        }
        __syncthreads();

        float s[8][4];
#pragma unroll
        for (int j = 0; j < 8; j++)
#pragma unroll
            for (int k = 0; k < 4; k++) s[j][k] = 0.f;

#pragma unroll
        for (int kk = 0; kk < 128; kk += 8) {
            int m0r = (warp*16 + r)*132;
            unsigned a0 = Qs[m0r + kk + cq];
            unsigned a1 = Qs[m0r + 8*132 + kk + cq];
            unsigned a2 = Qs[m0r + kk + cq + 4];
            unsigned a3 = Qs[m0r + 8*132 + kk + cq + 4];
#pragma unroll
            for (int j = 0; j < 8; j++) {
                unsigned b0 = Ks[(j*8 + r)*132 + kk + cq];
                unsigned b1 = Ks[(j*8 + r)*132 + kk + cq + 4];
                asm volatile(
                    "mma.sync.aligned.m16n8k8.row.col.f32.tf32.tf32.f32 "
                    "{%0,%1,%2,%3},{%4,%5,%6,%7},{%8,%9},{%0,%1,%2,%3};"
                    : "+f"(s[j][0]), "+f"(s[j][1]), "+f"(s[j][2]), "+f"(s[j][3])
                    : "r"(a0), "r"(a1), "r"(a2), "r"(a3), "r"(b0), "r"(b1));
            }
        }

        bool diag = (kb == qb);
        int lq0 = warp*16 + r;
        int lq1 = lq0 + 8;
#pragma unroll
        for (int j = 0; j < 8; j++) {
            int c0 = j*8 + cq*2, c1 = c0 + 1;
            s[j][0] *= scale; s[j][1] *= scale;
            s[j][2] *= scale; s[j][3] *= scale;
            if (diag) {
                if (c0 > lq0) s[j][0] = -1e9f;
                if (c1 > lq0) s[j][1] = -1e9f;
                if (c0 > lq1) s[j][2] = -1e9f;
                if (c1 > lq1) s[j][3] = -1e9f;
            }
        }

        float mt0 = -1e30f, mt1 = -1e30f;
#pragma unroll
        for (int j = 0; j < 8; j++) {
            mt0 = fmaxf(mt0, fmaxf(s[j][0], s[j][1]));
            mt1 = fmaxf(mt1, fmaxf(s[j][2], s[j][3]));
        }
        mt0 = fmaxf(mt0, __shfl_xor_sync(0xffffffffu, mt0, 1));
        mt0 = fmaxf(mt0, __shfl_xor_sync(0xffffffffu, mt0, 2));
        mt1 = fmaxf(mt1, __shfl_xor_sync(0xffffffffu, mt1, 1));
        mt1 = fmaxf(mt1, __shfl_xor_sync(0xffffffffu, mt1, 2));

        float mn0 = fmaxf(m0, mt0), mn1 = fmaxf(m1, mt1);
        float al0 = __expf(m0 - mn0), al1 = __expf(m1 - mn1);
        m0 = mn0; m1 = mn1;

        float ps0 = 0.f, ps1 = 0.f;
#pragma unroll
        for (int j = 0; j < 8; j++) {
            s[j][0] = __expf(s[j][0] - mn0);
            s[j][1] = __expf(s[j][1] - mn0);
            s[j][2] = __expf(s[j][2] - mn1);
            s[j][3] = __expf(s[j][3] - mn1);
            ps0 += s[j][0] + s[j][1];
            ps1 += s[j][2] + s[j][3];
        }
        ps0 += __shfl_xor_sync(0xffffffffu, ps0, 1);
        ps0 += __shfl_xor_sync(0xffffffffu, ps0, 2);
        ps1 += __shfl_xor_sync(0xffffffffu, ps1, 1);
        ps1 += __shfl_xor_sync(0xffffffffu, ps1, 2);
        l0 = l0 * al0 + ps0;
        l1 = l1 * al1 + ps1;

#pragma unroll
        for (int j = 0; j < 8; j++) {
            o[j][0] *= al0; o[j][1] *= al0;
            o[j][2] *= al1; o[j][3] *= al1;
        }

#pragma unroll
        for (int j = 0; j < 8; j++) {
            int c0 = j*8 + cq*2;
            Pw[r*68 + c0]       = f2tf(s[j][0]);
            Pw[r*68 + c0 + 1]   = f2tf(s[j][1]);
            Pw[(r+8)*68 + c0]     = f2tf(s[j][2]);
            Pw[(r+8)*68 + c0 + 1] = f2tf(s[j][3]);
        }
        __syncwarp();

#pragma unroll
        for (int kk = 0; kk < 64; kk += 8) {
            unsigned a0 = Pw[r*68 + kk + cq];
            unsigned a1 = Pw[(r+8)*68 + kk + cq];
            unsigned a2 = Pw[r*68 + kk + cq + 4];
            unsigned a3 = Pw[(r+8)*68 + kk + cq + 4];
#pragma unroll
            for (int j = 0; j < 8; j++) {
                unsigned b0 = Vs[(kk+cq)*68 + j*8 + r];
                unsigned b1 = Vs[(kk+cq+4)*68 + j*8 + r];
                asm volatile(
                    "mma.sync.aligned.m16n8k8.row.col.f32.tf32.tf32.f32 "
                    "{%0,%1,%2,%3},{%4,%5,%6,%7},{%8,%9},{%0,%1,%2,%3};"
                    : "+f"(o[j][0]), "+f"(o[j][1]), "+f"(o[j][2]), "+f"(o[j][3])
                    : "r"(a0), "r"(a1), "r"(a2), "r"(a3), "r"(b0), "r"(b1));
            }
        }
        __syncwarp();
    }

    float inv0 = 1.f / l0, inv1 = 1.f / l1;
    size_t row0 = (tq + warp*16 + r) * (size_t)(H_*DH_) + h*DH_;
    size_t row1 = row0 + (size_t)8 * (H_*DH_);
#pragma unroll
    for (int j = 0; j < 8; j++) {
        int c0 = j*8 + cq*2;
        float2 v0; v0.x = o[j][0]*inv0; v0.y = o[j][1]*inv0;
        float2 v1; v1.x = o[j][2]*inv1; v1.y = o[j][3]*inv1;
        *(float2*)&ctx[row0 + c0] = v0;
        *(float2*)&ctx[row1 + c0] = v1;
    }
}

// ---------------- misc elementwise ----------------------------------------
__global__ void zero_cnt_k(int* c) {
    if (threadIdx.x < NR_) c[threadIdx.x] = 0;
}

// z = blockIdx.y: slice; z<NR_ uses cntArr, shared slices dense (cnt=T_)
__global__ void silu_all_k(const float* __restrict__ g, const float* __restrict__ u,
                           float* __restrict__ o, const int* __restrict__ cntArr) {
    int z = blockIdx.y;
    int cnt = (z < NR_) ? cntArr[z] : T_;
    long i = (long)blockIdx.x * blockDim.x + threadIdx.x;
    if (i >= (long)cnt * DHID_) return;
    size_t base = (size_t)z * T_ * DHID_;
    float gv = g[base + i], uv = u[base + i];
    o[base + i] = (gv / (1.f + __expf(-gv))) * uv;
}

// ---------------- gating: logits + softmax + top2 + routing ----------------
__global__ void gate_topk_k(const float* __restrict__ h2, const float* __restrict__ gw,
                            int* __restrict__ cnt, int* __restrict__ elist,
                            int* __restrict__ rt, float* __restrict__ rw) {
    int t = blockIdx.x * 8 + (threadIdx.x >> 5);
    int lane = threadIdx.x & 31;
    if (t >= T_) return;
    float acc[NR_];
#pragma unroll
    for (int e = 0; e < NR_; e++) acc[e] = 0.f;
    const float* hr = h2 + (size_t)t * D_;
    for (int d = lane; d < D_; d += 32) {
        float xv = hr[d];
        const float* g = gw + (size_t)d * NR_;
#pragma unroll
        for (int e = 0; e < NR_; e++) acc[e] += xv * g[e];
    }
#pragma unroll
    for (int e = 0; e < NR_; e++)
#pragma unroll
        for (int off = 16; off; off >>= 1)
            acc[e] += __shfl_xor_sync(0xffffffffu, acc[e], off);
    if (lane == 0) {
        int i1 = 0;
#pragma unroll
        for (int e = 1; e < NR_; e++) if (acc[e] > acc[i1]) i1 = e;
        int i2 = (i1 == 0) ? 1 : 0;
#pragma unroll
        for (int e = 0; e < NR_; e++) {
            if (e == i1 || e == i2) continue;
            if (acc[e] > acc[i2]) i2 = e;
        }
        float p2 = __expf(acc[i2] - acc[i1]);
        float inv = 1.f / (1.f + p2);
        float w1 = inv, w2 = p2 * inv;
        int pos1 = atomicAdd(&cnt[i1], 1);
        elist[i1*T_ + pos1] = t;
        int pos2 = atomicAdd(&cnt[i2], 1);
        elist[i2*T_ + pos2] = t;
        rt[t*4+0] = i1; rt[t*4+1] = pos1;
        rt[t*4+2] = i2; rt[t*4+3] = pos2;
        rw[t*2+0] = w1; rw[t*2+1] = w2;
    }
}

// ------- final reduce: out += shared slices (8,9) + weighted routed --------
__global__ void reduce_k(float* __restrict__ out, const float* __restrict__ y,
                         const int* __restrict__ rt, const float* __restrict__ rw) {
    int t = blockIdx.x;
    int tid = threadIdx.x;
    int e1 = rt[t*4+0], p1 = rt[t*4+1];
    int e2 = rt[t*4+2], p2 = rt[t*4+3];
    float w1 = rw[t*2+0], w2 = rw[t*2+1];
    const float4* s0 = (const float4*)(y + ((size_t)(NR_+0)*T_ + t) * D_);
    const float4* s1 = (const float4*)(y + ((size_t)(NR_+1)*T_ + t) * D_);
    const float4* y1 = (const float4*)(y + ((size_t)e1*T_ + p1) * D_);
    const float4* y2 = (const float4*)(y + ((size_t)e2*T_ + p2) * D_);
    float4* op = (float4*)(out + (size_t)t * D_);
    for (int d = tid; d < D_/4; d += blockDim.x) {
        float4 o = op[d];
        float4 a = s0[d], b = s1[d], c = y1[d], e = y2[d];
        o.x += a.x + b.x + w1*c.x + w2*e.x;
        o.y += a.y + b.y + w1*c.y + w2*e.y;
        o.z += a.z + b.z + w1*c.z + w2*e.z;
        o.w += a.w + b.w + w1*c.w + w2*e.w;
        op[d] = o;
    }
}

// ---------------- launch ---------------------------------------------------
extern "C" void kernel_launch(void* const* d_in, const int* in_sizes, int n_in,
                              void* d_out, int out_size) {
    const float* x         = (const float*)d_in[0];
    const float* w_q       = (const float*)d_in[2];
    const float* w_dkv     = (const float*)d_in[3];
    const float* w_uk      = (const float*)d_in[4];
    const float* w_uv      = (const float*)d_in[5];
    const float* w_kr      = (const float*)d_in[6];
    const float* w_o       = (const float*)d_in[7];
    const float* attn_nw   = (const float*)d_in[8];
    const float* mlp_nw    = (const float*)d_in[9];
    const float* gate_w    = (const float*)d_in[10];
    const float* wr_gate   = (const float*)d_in[11];
    const float* wr_up     = (const float*)d_in[12];
    const float* wr_down   = (const float*)d_in[13];
    const float* ws_gate   = (const float*)d_in[14];
    const float* ws_up     = (const float*)d_in[15];
    const float* ws_down   = (const float*)d_in[16];
    float* out = (float*)d_out;

    float *ph, *pq, *plat, *pkc, *pv, *pkr, *pctx, *ph2;
    float *pgb, *pub, *py, *prw;
    int *pcnt, *pel, *prt;
    cudaGetSymbolAddress((void**)&ph,   g_h);
    cudaGetSymbolAddress((void**)&pq,   g_q);
    cudaGetSymbolAddress((void**)&plat, g_lat);
    cudaGetSymbolAddress((void**)&pkc,  g_kc);
    cudaGetSymbolAddress((void**)&pv,   g_v);
    cudaGetSymbolAddress((void**)&pkr,  g_kr);
    cudaGetSymbolAddress((void**)&pctx, g_ctx);
    cudaGetSymbolAddress((void**)&ph2,  g_h2);
    cudaGetSymbolAddress((void**)&pgb,  g_gb);
    cudaGetSymbolAddress((void**)&pub,  g_ub);
    cudaGetSymbolAddress((void**)&py,   g_y);
    cudaGetSymbolAddress((void**)&pcnt, g_cnt);
    cudaGetSymbolAddress((void**)&pel,  g_elist);
    cudaGetSymbolAddress((void**)&prt,  g_rt);
    cudaGetSymbolAddress((void**)&prw,  g_rw);

    cudaFuncSetAttribute(flash_mma_k,
                         cudaFuncAttributeMaxDynamicSharedMemorySize, FA_SMEM_BYTES);
    cudaFuncSetAttribute(mma_multi4,
                         cudaFuncAttributeMaxDynamicSharedMemorySize, MM_SMEM_BYTES);
    cudaFuncSetAttribute(mma_gu_all,
                         cudaFuncAttributeMaxDynamicSharedMemorySize, MM_SMEM_BYTES);
    cudaFuncSetAttribute(mma_down_all,
                         cudaFuncAttributeMaxDynamicSharedMemorySize, MM_SMEM_BYTES);

    // 1) h = rmsnorm(x)
    rmsnorm_k<<<T_, 256>>>(x, attn_nw, ph);

    // 2) fused projections: w_q (16 tiles) + w_dkv (4) + w_kr (1)
    mma_multi4<<<dim3(21, T_/128), 256, MM_SMEM_BYTES>>>(ph, D_,
        w_q,   pq,   H_*QDIM_, 16,
        w_dkv, plat, DL_,      4,
        w_kr,  pkr,  DR_,      1,
        nullptr, nullptr, 0, 0, nullptr);

    // 3) RoPE
    {
        int n = T_*H_*32 + T_*32;
        rope_k<<<(n + 255)/256, 256>>>(pq, pkr);
    }

    // 4) fused k_c + v up-projections
    mma_multi4<<<dim3(16, T_/128), 256, MM_SMEM_BYTES>>>(plat, DL_,
        w_uk, pkc, H_*DH_, 8,
        w_uv, pv,  H_*DH_, 8,
        nullptr, nullptr, 0, 0,
        nullptr, nullptr, 0, 0, nullptr);

    // 5) attention (R11 config: 64 q-rows/CTA, 4 warps)
    flash_mma_k<<<dim3(S_/64, B_*H_), 128, FA_SMEM_BYTES>>>(pq, pkc, pkr, pv, pctx);

    // 6) out = x + ctx @ w_o
    mma_multi4<<<dim3(8, T_/128), 256, MM_SMEM_BYTES>>>(pctx, H_*DH_,
        w_o, out, D_, 8,
        nullptr, nullptr, 0, 0,
        nullptr, nullptr, 0, 0,
        nullptr, nullptr, 0, 0, x);

    // 7) h2 = rmsnorm(out)
    rmsnorm_k<<<T_, 256>>>(out, mlp_nw, ph2);

    // 8) routing
    zero_cnt_k<<<1, 32>>>(pcnt);
    gate_topk_k<<<T_/8, 256>>>(ph2, gate_w, pcnt, pel, prt, prw);

    // 9) unified experts: 10 slices (8 routed + 2 shared) per launch
    mma_gu_all<<<dim3(2*DHID_/128, T_/128, NE_), 256, MM_SMEM_BYTES>>>(
        ph2, wr_gate, wr_up, ws_gate, ws_up, pgb, pub, pel, pcnt);
    silu_all_k<<<dim3((T_*DHID_ + 255)/256, NE_), 256>>>(pgb, pub, pgb, pcnt);
    mma_down_all<<<dim3(D_/128, T_/128, NE_), 256, MM_SMEM_BYTES>>>(
        pgb, wr_down, ws_down, py, pcnt);

    // 10) deterministic combine
    reduce_k<<<T_, 256>>>(out, py, prt, prw);
}

// round 17
// speedup vs baseline: 1.2641x; 1.0703x over previous
#include <cuda_runtime.h>
#include <math.h>

#define B_ 2
#define S_ 2048
#define D_ 1024
#define H_ 16
#define DH_ 64
#define DR_ 64
#define DL_ 512
#define DHID_ 512
#define NR_ 8
#define NS_ 2
#define NE_ (NR_+NS_)       // 10 expert slices (8 routed + 2 shared)
#define T_ (B_*S_)          // 4096 tokens
#define QDIM_ (DH_+DR_)     // 128

// ---------------- scratch (device globals; no allocation allowed) ----------
__device__ float g_h  [T_*D_];
__device__ float g_q  [T_*H_*QDIM_];
__device__ float g_lat[T_*DL_];
__device__ float g_kc [T_*H_*DH_];
__device__ float g_v  [T_*H_*DH_];
__device__ float g_kr [T_*DR_];
__device__ float g_ctx[T_*H_*DH_];
__device__ float g_h2 [T_*D_];
__device__ int   g_cnt[NR_];
__device__ int   g_elist[NR_*T_];
__device__ int   g_rt  [T_*4];        // per-token (e1,pos1,e2,pos2)
__device__ float g_rw  [T_*2];        // per-token (w1,w2)
// unified expert buffers: slices 0..7 routed (compact rows), 8..9 shared (dense)
__device__ float g_gb [NE_*T_*DHID_];   // holds fused silu(gate)*up
__device__ float g_y  [NE_*T_*D_];

__device__ __forceinline__ unsigned f2tf(float x) {
    unsigned r;
    asm("cvt.rna.tf32.f32 %0, %1;" : "=r"(r) : "f"(x));
    return r;
}

__device__ __forceinline__ void cp16(float* dst, const float* src) {
    unsigned d = (unsigned)__cvta_generic_to_shared(dst);
    asm volatile("cp.async.cg.shared.global [%0], [%1], 16;" :: "r"(d), "l"(src));
}

// ---------------- rmsnorm --------------------------------------------------
__global__ void rmsnorm_k(const float* __restrict__ x, const float* __restrict__ w,
                          float* __restrict__ o) {
    int row = blockIdx.x;
    const float* xr = x + (size_t)row * D_;
    float ss = 0.f;
    float vloc[4];
#pragma unroll
    for (int i = 0; i < 4; i++) { vloc[i] = xr[threadIdx.x + i*256]; ss += vloc[i]*vloc[i]; }
#pragma unroll
    for (int off = 16; off; off >>= 1) ss += __shfl_xor_sync(0xffffffffu, ss, off);
    __shared__ float sm[8];
    __shared__ float invs;
    if ((threadIdx.x & 31) == 0) sm[threadIdx.x >> 5] = ss;
    __syncthreads();
    if (threadIdx.x == 0) {
        float t = 0.f;
#pragma unroll
        for (int i = 0; i < 8; i++) t += sm[i];
        invs = 1.0f / sqrtf(t / (float)D_ + 1e-6f);
    }
    __syncthreads();
    float inv = invs;
    float* orow = o + (size_t)row * D_;
#pragma unroll
    for (int i = 0; i < 4; i++) {
        int d = threadIdx.x + i*256;
        orow[d] = vloc[i] * inv * w[d];
    }
}

// ---------------- tf32 mma core: 128x128x16, 4-stage cp.async --------------
#define STG_ 4
#define SA_STRIDE 20                 // 16 k + 4 pad
#define SB_STRIDE 136                // 128 n + 8 pad
#define SA_SZ (128*SA_STRIDE)
#define SB_SZ (16*SB_STRIDE)
#define STG_SZ (SA_SZ + SB_SZ)
#define MM_SMEM_BYTES (STG_*STG_SZ*4)   // 75,776 B

__device__ __forceinline__ void mma_core(
        const float* __restrict__ A, const float* __restrict__ Bm,
        float* __restrict__ C, int N, int K, int bx, int by,
        int cnt, const int* __restrict__ idx, const float* __restrict__ Dadd) {
    extern __shared__ float smdyn[];

    int tid = threadIdx.x;
    int warp = tid >> 5, lane = tid & 31;
    int wm = warp & 3;
    int wn = warp >> 2;
    int r  = lane >> 2;
    int cq = lane & 3;

    float acc[2][8][4];
#pragma unroll
    for (int i = 0; i < 2; i++)
#pragma unroll
        for (int j = 0; j < 8; j++)
#pragma unroll
            for (int k = 0; k < 4; k++) acc[i][j][k] = 0.f;

    int ar = tid >> 1;
    int ak = (tid & 1) * 8;
    int gRowA = by*128 + ar;
    int rowA;
    if (idx) {
        int rs = (cnt >= 0 && gRowA >= cnt) ? (cnt - 1) : gRowA;
        rowA = idx[rs];
    } else if (cnt >= 0) {
        rowA = (gRowA < cnt) ? gRowA : (cnt - 1);
    } else {
        rowA = gRowA;
    }
    const float* Arow = A + (size_t)rowA * K + ak;
    int aDstOff = ar*SA_STRIDE + ak;

    int br = tid >> 4;
    int bc = (tid & 15) * 8;
    int bcc = (bc + 8 <= N) ? bc : (N - 8);
    const float* Bsrc0 = Bm + (size_t)br * N + (size_t)bx*128 + bcc;
    int bDstOff = SA_SZ + br*SB_STRIDE + bc;

    int ntiles = K >> 4;

#pragma unroll
    for (int p = 0; p < STG_-1; p++) {
        float* st = smdyn + p*STG_SZ;
        const float* as = Arow + p*16;
        cp16(st + aDstOff,     as);
        cp16(st + aDstOff + 4, as + 4);
        const float* bs = Bsrc0 + (size_t)p * 16 * N;
        cp16(st + bDstOff,     bs);
        cp16(st + bDstOff + 4, bs + 4);
        asm volatile("cp.async.commit_group;");
    }

    for (int kt = 0; kt < ntiles; kt++) {
        asm volatile("cp.async.wait_group %0;" :: "n"(STG_-2));
        __syncthreads();

        const unsigned* As = (const unsigned*)(smdyn + (kt & (STG_-1))*STG_SZ);
        const unsigned* Bs = As + SA_SZ;

#pragma unroll
        for (int kk = 0; kk < 16; kk += 8) {
            unsigned a[2][4];
#pragma unroll
            for (int i = 0; i < 2; i++) {
                int m0 = (wm*32 + i*16 + r) * SA_STRIDE;
                a[i][0] = As[m0                + kk + cq];
                a[i][1] = As[m0 + 8*SA_STRIDE  + kk + cq];
                a[i][2] = As[m0                + kk + cq + 4];
                a[i][3] = As[m0 + 8*SA_STRIDE  + kk + cq + 4];
            }
#pragma unroll
            for (int j = 0; j < 8; j++) {
                int n0 = wn*64 + j*8 + r;
                unsigned b0 = Bs[(kk+cq  )*SB_STRIDE + n0];
                unsigned b1 = Bs[(kk+cq+4)*SB_STRIDE + n0];
#pragma unroll
                for (int i = 0; i < 2; i++) {
                    asm volatile(
                        "mma.sync.aligned.m16n8k8.row.col.f32.tf32.tf32.f32 "
                        "{%0,%1,%2,%3},{%4,%5,%6,%7},{%8,%9},{%0,%1,%2,%3};"
                        : "+f"(acc[i][j][0]), "+f"(acc[i][j][1]),
                          "+f"(acc[i][j][2]), "+f"(acc[i][j][3])
                        : "r"(a[i][0]), "r"(a[i][1]), "r"(a[i][2]), "r"(a[i][3]),
                          "r"(b0), "r"(b1));
                }
            }
        }

        int kn = kt + STG_ - 1;
        if (kn < ntiles) {
            float* st = smdyn + (kn & (STG_-1))*STG_SZ;
            const float* as = Arow + kn*16;
            cp16(st + aDstOff,     as);
            cp16(st + aDstOff + 4, as + 4);
            const float* bs = Bsrc0 + (size_t)kn * 16 * N;
            cp16(st + bDstOff,     bs);
            cp16(st + bDstOff + 4, bs + 4);
        }
        asm volatile("cp.async.commit_group;");
    }

#pragma unroll
    for (int i = 0; i < 2; i++) {
        int lrow = wm*32 + i*16 + r;
        int gr0 = by*128 + lrow;
        int gr1 = gr0 + 8;
#pragma unroll
        for (int half = 0; half < 2; half++) {
            int gr = half ? gr1 : gr0;
            if (cnt >= 0 && gr >= cnt) continue;
            float* cbase = C + (size_t)gr * N + (size_t)bx*128 + wn*64;
            const float* dbase = Dadd ? (Dadd + (size_t)gr * N + (size_t)bx*128 + wn*64)
                                      : nullptr;
#pragma unroll
            for (int j = 0; j < 8; j++) {
                int ncol = wn*64 + j*8 + cq*2;
                if (bx*128 + ncol >= N && N < 128) continue;
                float v0 = acc[i][j][half*2 + 0];
                float v1 = acc[i][j][half*2 + 1];
                float2* p = (float2*)(cbase + j*8 + cq*2);
                if (dbase) {
                    float2 dv = *(const float2*)(dbase + j*8 + cq*2);
                    float2 nv; nv.x = dv.x + v0; nv.y = dv.y + v1;
                    *p = nv;
                } else {
                    float2 nv; nv.x = v0; nv.y = v1;
                    *p = nv;
                }
            }
        }
    }
}

// ---- dense multi-segment (same A, up to 4 (B,C,N) segments along grid.x) --
__global__ __launch_bounds__(256, 2) void mma_multi4(
        const float* __restrict__ A, int K,
        const float* B0, float* C0, int N0, int X0,
        const float* B1, float* C1, int N1, int X1,
        const float* B2, float* C2, int N2, int X2,
        const float* B3, float* C3, int N3, int X3,
        const float* __restrict__ Dadd) {
    int bx = blockIdx.x;
    const float* Bm; float* C; int N;
    if (bx < X0)                { Bm = B0; C = C0; N = N0; }
    else if (bx < X0+X1)        { bx -= X0; Bm = B1; C = C1; N = N1; }
    else if (bx < X0+X1+X2)     { bx -= X0+X1; Bm = B2; C = C2; N = N2; }
    else                        { bx -= X0+X1+X2; Bm = B3; C = C3; N = N3; }
    mma_core(A, Bm, C, N, K, bx, blockIdx.y, -1, nullptr, Dadd);
}

// ---- fused gate+up+silu: CTA computes 128x64 gate AND 128x64 up tiles -----
// warp tile: 32m x 32n of each; out = silu(g)*u -> gb slice. z = expert slice.
__global__ __launch_bounds__(256, 2) void mma_gu_all(
        const float* __restrict__ h2,
        const float* __restrict__ wr_gate, const float* __restrict__ wr_up,
        const float* __restrict__ ws_gate, const float* __restrict__ ws_up,
        float* __restrict__ gb,
        const int* __restrict__ elist, const int* __restrict__ cntArr) {
    extern __shared__ float smdyn[];
    int z = blockIdx.z;
    int cnt = -1;
    const int* idx = nullptr;
    const float* Wg; const float* Wu;
    if (z < NR_) {
        cnt = cntArr[z];
        if ((int)blockIdx.y * 128 >= cnt) return;
        idx = elist + z*T_;
        Wg = wr_gate + (size_t)z*D_*DHID_;
        Wu = wr_up   + (size_t)z*D_*DHID_;
    } else {
        Wg = ws_gate + (size_t)(z-NR_)*D_*DHID_;
        Wu = ws_up   + (size_t)(z-NR_)*D_*DHID_;
    }
    int bx = blockIdx.x;          // 0..7, n-range = bx*64 .. bx*64+63
    int by = blockIdx.y;

    int tid = threadIdx.x;
    int warp = tid >> 5, lane = tid & 31;
    int wm = warp & 3;
    int wn = warp >> 2;           // 0..1, n-offset wn*32
    int r  = lane >> 2;
    int cq = lane & 3;

    float accg[2][4][4], accu[2][4][4];
#pragma unroll
    for (int i = 0; i < 2; i++)
#pragma unroll
        for (int j = 0; j < 4; j++)
#pragma unroll
            for (int k = 0; k < 4; k++) { accg[i][j][k] = 0.f; accu[i][j][k] = 0.f; }

    // A loader (identical to mma_core)
    int ar = tid >> 1;
    int ak = (tid & 1) * 8;
    int gRowA = by*128 + ar;
    int rowA;
    if (idx) {
        int rs = (cnt >= 0 && gRowA >= cnt) ? (cnt - 1) : gRowA;
        rowA = idx[rs];
    } else {
        rowA = gRowA;
    }
    const float* Arow = h2 + (size_t)rowA * D_ + ak;
    int aDstOff = ar*SA_STRIDE + ak;

    // B loader: smem cols 0..63 = gate n-range, 64..127 = up n-range
    int br = tid >> 4;
    int bc = (tid & 15) * 8;
    const float* Bsrc0;
    if (bc < 64) Bsrc0 = Wg + (size_t)br * DHID_ + (size_t)bx*64 + bc;
    else         Bsrc0 = Wu + (size_t)br * DHID_ + (size_t)bx*64 + (bc - 64);
    int bDstOff = SA_SZ + br*SB_STRIDE + bc;

    const int ntiles = D_ >> 4;   // 64

#pragma unroll
    for (int p = 0; p < STG_-1; p++) {
        float* st = smdyn + p*STG_SZ;
        const float* as = Arow + p*16;
        cp16(st + aDstOff,     as);
        cp16(st + aDstOff + 4, as + 4);
        const float* bs = Bsrc0 + (size_t)p * 16 * DHID_;
        cp16(st + bDstOff,     bs);
        cp16(st + bDstOff + 4, bs + 4);
        asm volatile("cp.async.commit_group;");
    }

    for (int kt = 0; kt < ntiles; kt++) {
        asm volatile("cp.async.wait_group %0;" :: "n"(STG_-2));
        __syncthreads();

        const unsigned* As = (const unsigned*)(smdyn + (kt & (STG_-1))*STG_SZ);
        const unsigned* Bs = As + SA_SZ;

#pragma unroll
        for (int kk = 0; kk < 16; kk += 8) {
            unsigned a[2][4];
#pragma unroll
            for (int i = 0; i < 2; i++) {
                int m0 = (wm*32 + i*16 + r) * SA_STRIDE;
                a[i][0] = As[m0                + kk + cq];
                a[i][1] = As[m0 + 8*SA_STRIDE  + kk + cq];
                a[i][2] = As[m0                + kk + cq + 4];
                a[i][3] = As[m0 + 8*SA_STRIDE  + kk + cq + 4];
            }
#pragma unroll
            for (int j = 0; j < 4; j++) {
                int n0 = wn*32 + j*8 + r;
                unsigned bg0 = Bs[(kk+cq  )*SB_STRIDE + n0];
                unsigned bg1 = Bs[(kk+cq+4)*SB_STRIDE + n0];
                unsigned bu0 = Bs[(kk+cq  )*SB_STRIDE + 64 + n0];
                unsigned bu1 = Bs[(kk+cq+4)*SB_STRIDE + 64 + n0];
#pragma unroll
                for (int i = 0; i < 2; i++) {
                    asm volatile(
                        "mma.sync.aligned.m16n8k8.row.col.f32.tf32.tf32.f32 "
                        "{%0,%1,%2,%3},{%4,%5,%6,%7},{%8,%9},{%0,%1,%2,%3};"
                        : "+f"(accg[i][j][0]), "+f"(accg[i][j][1]),
                          "+f"(accg[i][j][2]), "+f"(accg[i][j][3])
                        : "r"(a[i][0]), "r"(a[i][1]), "r"(a[i][2]), "r"(a[i][3]),
                          "r"(bg0), "r"(bg1));
                    asm volatile(
                        "mma.sync.aligned.m16n8k8.row.col.f32.tf32.tf32.f32 "
                        "{%0,%1,%2,%3},{%4,%5,%6,%7},{%8,%9},{%0,%1,%2,%3};"
                        : "+f"(accu[i][j][0]), "+f"(accu[i][j][1]),
                          "+f"(accu[i][j][2]), "+f"(accu[i][j][3])
                        : "r"(a[i][0]), "r"(a[i][1]), "r"(a[i][2]), "r"(a[i][3]),
                          "r"(bu0), "r"(bu1));
                }
            }
        }

        int kn = kt + STG_ - 1;
        if (kn < ntiles) {
            float* st = smdyn + (kn & (STG_-1))*STG_SZ;
            const float* as = Arow + kn*16;
            cp16(st + aDstOff,     as);
            cp16(st + aDstOff + 4, as + 4);
            const float* bs = Bsrc0 + (size_t)kn * 16 * DHID_;
            cp16(st + bDstOff,     bs);
            cp16(st + bDstOff + 4, bs + 4);
        }
        asm volatile("cp.async.commit_group;");
    }

    // epilogue: write silu(g)*u (128 x 64 tile)
    float* Cs = gb + (size_t)z*T_*DHID_;
#pragma unroll
    for (int i = 0; i < 2; i++) {
        int lrow = wm*32 + i*16 + r;
        int gr0 = by*128 + lrow;
        int gr1 = gr0 + 8;
#pragma unroll
        for (int half = 0; half < 2; half++) {
            int gr = half ? gr1 : gr0;
            if (cnt >= 0 && gr >= cnt) continue;
            float* cbase = Cs + (size_t)gr * DHID_ + (size_t)bx*64 + wn*32;
#pragma unroll
            for (int j = 0; j < 4; j++) {
                float gv0 = accg[i][j][half*2 + 0];
                float gv1 = accg[i][j][half*2 + 1];
                float uv0 = accu[i][j][half*2 + 0];
                float uv1 = accu[i][j][half*2 + 1];
                float2 nv;
                nv.x = (gv0 / (1.f + __expf(-gv0))) * uv0;
                nv.y = (gv1 / (1.f + __expf(-gv1))) * uv1;
                *(float2*)(cbase + j*8 + cq*2) = nv;
            }
        }
    }
}

// ---- unified experts: down, compact/dense in -> same out slice ------------
__global__ __launch_bounds__(256, 2) void mma_down_all(
        const float* __restrict__ gb,
        const float* __restrict__ wr_down, const float* __restrict__ ws_down,
        float* __restrict__ y, const int* __restrict__ cntArr) {
    int z = blockIdx.z;
    int cnt = -1;
    const float* Wd;
    if (z < NR_) {
        cnt = cntArr[z];
        if ((int)blockIdx.y * 128 >= cnt) return;
        Wd = wr_down + (size_t)z*DHID_*D_;
    } else {
        Wd = ws_down + (size_t)(z-NR_)*DHID_*D_;
    }
    mma_core(gb + (size_t)z*T_*DHID_, Wd, y + (size_t)z*T_*D_,
             D_, DHID_, blockIdx.x, blockIdx.y, cnt, nullptr, nullptr);
}

// ---------------- RoPE (in-place on q tail + k_r) --------------------------
__global__ void rope_k(float* __restrict__ q, float* __restrict__ kr) {
    int p = blockIdx.x * blockDim.x + threadIdx.x;
    const int NQ = T_ * H_ * 32;
    const int NK = T_ * 32;
    if (p < NQ) {
        int i = p & 31;
        int h = (p >> 5) & (H_ - 1);
        int t = p >> 9;
        int s = t & (S_ - 1);
        float inv = powf(10000.0f, -(float)i / 32.0f);
        float sn, c;
        sincosf((float)s * inv, &sn, &c);
        float* base = q + (size_t)t * (H_*QDIM_) + h * QDIM_ + DH_;
        float t1 = base[i], t2 = base[32 + i];
        base[i]      = t1 * c - t2 * sn;
        base[32 + i] = t2 * c + t1 * sn;
    } else if (p < NQ + NK) {
        int p2 = p - NQ;
        int i = p2 & 31;
        int t = p2 >> 5;
        int s = t & (S_ - 1);
        float inv = powf(10000.0f, -(float)i / 32.0f);
        float sn, c;
        sincosf((float)s * inv, &sn, &c);
        float* base = kr + (size_t)t * DR_;
        float t1 = base[i], t2 = base[32 + i];
        base[i]      = t1 * c - t2 * sn;
        base[32 + i] = t2 * c + t1 * sn;
    }
}

// ------- tensor-core flash attention (64 q-rows/CTA, 4 warps) --------------
#define FA_SMEM_FLOATS (64*132 + 64*132 + 64*68 + 4*16*68)
#define FA_SMEM_BYTES  (FA_SMEM_FLOATS*4)

__global__ __launch_bounds__(128) void flash_mma_k(
        const float* __restrict__ q, const float* __restrict__ kc,
        const float* __restrict__ kr, const float* __restrict__ v,
        float* __restrict__ ctx) {
    extern __shared__ unsigned smbuf[];
    unsigned* Qs = smbuf;                 // [64][132]
    unsigned* Ks = Qs + 64*132;           // [64][132]
    unsigned* Vs = Ks + 64*132;           // [64][68]
    unsigned* Ps = Vs + 64*68;            // [4][16][68]

    int qb = (int)gridDim.x - 1 - (int)blockIdx.x;   // longest CTAs first
    int bh = blockIdx.y;
    int b = bh >> 4, h = bh & 15;
    int tid = threadIdx.x;
    int warp = tid >> 5, lane = tid & 31;
    int r = lane >> 2, cq = lane & 3;
    size_t tq = (size_t)b*S_ + qb*64;
    unsigned* Pw = Ps + warp*16*68;

#pragma unroll
    for (int i = 0; i < 16; i++) {
        int e = i*128 + tid;
        int row = e >> 5, c4 = (e & 31) * 4;
        float4 qv = *(const float4*)&q[(tq+row)*(size_t)(H_*QDIM_) + h*QDIM_ + c4];
        unsigned* dst = &Qs[row*132 + c4];
        dst[0]=f2tf(qv.x); dst[1]=f2tf(qv.y); dst[2]=f2tf(qv.z); dst[3]=f2tf(qv.w);
    }

    float m0 = -1e30f, m1 = -1e30f;
    float l0 = 0.f,  l1 = 0.f;
    float o[8][4];
#pragma unroll
    for (int j = 0; j < 8; j++)
#pragma unroll
        for (int k = 0; k < 4; k++) o[j][k] = 0.f;

    const float scale = 0.088388347648318447f;   // 1/sqrt(128)
    int nkb = qb + 1;

    for (int kb = 0; kb < nkb; kb++) {
        size_t tk = (size_t)b*S_ + kb*64;
        __syncthreads();
#pragma unroll
        for (int i = 0; i < 8; i++) {
            int e = i*128 + tid;
            int row = e >> 4, c4 = (e & 15) * 4;
            float4 kv = *(const float4*)&kc[(tk+row)*(size_t)(H_*DH_) + h*DH_ + c4];
            unsigned* dst = &Ks[row*132 + c4];
            dst[0]=f2tf(kv.x); dst[1]=f2tf(kv.y); dst[2]=f2tf(kv.z); dst[3]=f2tf(kv.w);
        }
#pragma unroll
        for (int i = 0; i < 8; i++) {
            int e = i*128 + tid;
            int row = e >> 4, c4 = (e & 15) * 4;
            float4 kv = *(const float4*)&kr[(tk+row)*(size_t)DR_ + c4];
            unsigned* dst = &Ks[row*132 + 64 + c4];
            dst[0]=f2tf(kv.x); dst[1]=f2tf(kv.y); dst[2]=f2tf(kv.z); dst[3]=f2tf(kv.w);
        }
#pragma unroll
        for (int i = 0; i < 8; i++) {
            int e = i*128 + tid;
            int row = e >> 4, c4 = (e & 15) * 4;
            float4 vv = *(const float4*)&v[(tk+row)*(size_t)(H_*DH_) + h*DH_ + c4];
            unsigned* dst = &Vs[row*68 + c4];
            dst[0]=f2tf(vv.x); dst[1]=f2tf(vv.y); dst[2]=f2tf(vv.z); dst[3]=f2tf(vv.w);
        }
        __syncthreads();

        float s[8][4];
#pragma unroll
        for (int j = 0; j < 8; j++)
#pragma unroll
            for (int k = 0; k < 4; k++) s[j][k] = 0.f;

#pragma unroll
        for (int kk = 0; kk < 128; kk += 8) {
            int m0r = (warp*16 + r)*132;
            unsigned a0 = Qs[m0r + kk + cq];
            unsigned a1 = Qs[m0r + 8*132 + kk + cq];
            unsigned a2 = Qs[m0r + kk + cq + 4];
            unsigned a3 = Qs[m0r + 8*132 + kk + cq + 4];
#pragma unroll
            for (int j = 0; j < 8; j++) {
                unsigned b0 = Ks[(j*8 + r)*132 + kk + cq];
                unsigned b1 = Ks[(j*8 + r)*132 + kk + cq + 4];
                asm volatile(
                    "mma.sync.aligned.m16n8k8.row.col.f32.tf32.tf32.f32 "
                    "{%0,%1,%2,%3},{%4,%5,%6,%7},{%8,%9},{%0,%1,%2,%3};"
                    : "+f"(s[j][0]), "+f"(s[j][1]), "+f"(s[j][2]), "+f"(s[j][3])
                    : "r"(a0), "r"(a1), "r"(a2), "r"(a3), "r"(b0), "r"(b1));
            }
        }

        bool diag = (kb == qb);
        int lq0 = warp*16 + r;
        int lq1 = lq0 + 8;
#pragma unroll
        for (int j = 0; j < 8; j++) {
            int c0 = j*8 + cq*2, c1 = c0 + 1;
            s[j][0] *= scale; s[j][1] *= scale;
            s[j][2] *= scale; s[j][3] *= scale;
            if (diag) {
                if (c0 > lq0) s[j][0] = -1e9f;
                if (c1 > lq0) s[j][1] = -1e9f;
                if (c0 > lq1) s[j][2] = -1e9f;
                if (c1 > lq1) s[j][3] = -1e9f;
            }
        }

        float mt0 = -1e30f, mt1 = -1e30f;
#pragma unroll
        for (int j = 0; j < 8; j++) {
            mt0 = fmaxf(mt0, fmaxf(s[j][0], s[j][1]));
            mt1 = fmaxf(mt1, fmaxf(s[j][2], s[j][3]));
        }
        mt0 = fmaxf(mt0, __shfl_xor_sync(0xffffffffu, mt0, 1));
        mt0 = fmaxf(mt0, __shfl_xor_sync(0xffffffffu, mt0, 2));
        mt1 = fmaxf(mt1, __shfl_xor_sync(0xffffffffu, mt1, 1));
        mt1 = fmaxf(mt1, __shfl_xor_sync(0xffffffffu, mt1, 2));

        float mn0 = fmaxf(m0, mt0), mn1 = fmaxf(m1, mt1);
        float al0 = __expf(m0 - mn0), al1 = __expf(m1 - mn1);
        m0 = mn0; m1 = mn1;

        float ps0 = 0.f, ps1 = 0.f;
#pragma unroll
        for (int j = 0; j < 8; j++) {
            s[j][0] = __expf(s[j][0] - mn0);
            s[j][1] = __expf(s[j][1] - mn0);
            s[j][2] = __expf(s[j][2] - mn1);
            s[j][3] = __expf(s[j][3] - mn1);
            ps0 += s[j][0] + s[j][1];
            ps1 += s[j][2] + s[j][3];
        }
        ps0 += __shfl_xor_sync(0xffffffffu, ps0, 1);
        ps0 += __shfl_xor_sync(0xffffffffu, ps0, 2);
        ps1 += __shfl_xor_sync(0xffffffffu, ps1, 1);
        ps1 += __shfl_xor_sync(0xffffffffu, ps1, 2);
        l0 = l0 * al0 + ps0;
        l1 = l1 * al1 + ps1;

#pragma unroll
        for (int j = 0; j < 8; j++) {
            o[j][0] *= al0; o[j][1] *= al0;
            o[j][2] *= al1; o[j][3] *= al1;
        }

#pragma unroll
        for (int j = 0; j < 8; j++) {
            int c0 = j*8 + cq*2;
            Pw[r*68 + c0]       = f2tf(s[j][0]);
            Pw[r*68 + c0 + 1]   = f2tf(s[j][1]);
            Pw[(r+8)*68 + c0]     = f2tf(s[j][2]);
            Pw[(r+8)*68 + c0 + 1] = f2tf(s[j][3]);
        }
        __syncwarp();

#pragma unroll
        for (int kk = 0; kk < 64; kk += 8) {
            unsigned a0 = Pw[r*68 + kk + cq];
            unsigned a1 = Pw[(r+8)*68 + kk + cq];
            unsigned a2 = Pw[r*68 + kk + cq + 4];
            unsigned a3 = Pw[(r+8)*68 + kk + cq + 4];
#pragma unroll
            for (int j = 0; j < 8; j++) {
                unsigned b0 = Vs[(kk+cq)*68 + j*8 + r];
                unsigned b1 = Vs[(kk+cq+4)*68 + j*8 + r];
                asm volatile(
                    "mma.sync.aligned.m16n8k8.row.col.f32.tf32.tf32.f32 "
                    "{%0,%1,%2,%3},{%4,%5,%6,%7},{%8,%9},{%0,%1,%2,%3};"
                    : "+f"(o[j][0]), "+f"(o[j][1]), "+f"(o[j][2]), "+f"(o[j][3])
                    : "r"(a0), "r"(a1), "r"(a2), "r"(a3), "r"(b0), "r"(b1));
            }
        }
        __syncwarp();
    }

    float inv0 = 1.f / l0, inv1 = 1.f / l1;
    size_t row0 = (tq + warp*16 + r) * (size_t)(H_*DH_) + h*DH_;
    size_t row1 = row0 + (size_t)8 * (H_*DH_);
#pragma unroll
    for (int j = 0; j < 8; j++) {
        int c0 = j*8 + cq*2;
        float2 v0; v0.x = o[j][0]*inv0; v0.y = o[j][1]*inv0;
        float2 v1; v1.x = o[j][2]*inv1; v1.y = o[j][3]*inv1;
        *(float2*)&ctx[row0 + c0] = v0;
        *(float2*)&ctx[row1 + c0] = v1;
    }
}

// ---------------- misc ------------------------------------------------------
__global__ void zero_cnt_k(int* c) {
    if (threadIdx.x < NR_) c[threadIdx.x] = 0;
}

// ---------------- gating: logits + softmax + top2 + routing ----------------
__global__ void gate_topk_k(const float* __restrict__ h2, const float* __restrict__ gw,
                            int* __restrict__ cnt, int* __restrict__ elist,
                            int* __restrict__ rt, float* __restrict__ rw) {
    int t = blockIdx.x * 8 + (threadIdx.x >> 5);
    int lane = threadIdx.x & 31;
    if (t >= T_) return;
    float acc[NR_];
#pragma unroll
    for (int e = 0; e < NR_; e++) acc[e] = 0.f;
    const float* hr = h2 + (size_t)t * D_;
    for (int d = lane; d < D_; d += 32) {
        float xv = hr[d];
        const float* g = gw + (size_t)d * NR_;
#pragma unroll
        for (int e = 0; e < NR_; e++) acc[e] += xv * g[e];
    }
#pragma unroll
    for (int e = 0; e < NR_; e++)
#pragma unroll
        for (int off = 16; off; off >>= 1)
            acc[e] += __shfl_xor_sync(0xffffffffu, acc[e], off);
    if (lane == 0) {
        int i1 = 0;
#pragma unroll
        for (int e = 1; e < NR_; e++) if (acc[e] > acc[i1]) i1 = e;
        int i2 = (i1 == 0) ? 1 : 0;
#pragma unroll
        for (int e = 0; e < NR_; e++) {
            if (e == i1 || e == i2) continue;
            if (acc[e] > acc[i2]) i2 = e;
        }
        float p2 = __expf(acc[i2] - acc[i1]);
        float inv = 1.f / (1.f + p2);
        float w1 = inv, w2 = p2 * inv;
        int pos1 = atomicAdd(&cnt[i1], 1);
        elist[i1*T_ + pos1] = t;
        int pos2 = atomicAdd(&cnt[i2], 1);
        elist[i2*T_ + pos2] = t;
        rt[t*4+0] = i1; rt[t*4+1] = pos1;
        rt[t*4+2] = i2; rt[t*4+3] = pos2;
        rw[t*2+0] = w1; rw[t*2+1] = w2;
    }
}

// ------- final reduce: out += shared slices (8,9) + weighted routed --------
__global__ void reduce_k(float* __restrict__ out, const float* __restrict__ y,
                         const int* __restrict__ rt, const float* __restrict__ rw) {
    int t = blockIdx.x;
    int tid = threadIdx.x;
    int e1 = rt[t*4+0], p1 = rt[t*4+1];
    int e2 = rt[t*4+2], p2 = rt[t*4+3];
    float w1 = rw[t*2+0], w2 = rw[t*2+1];
    const float4* s0 = (const float4*)(y + ((size_t)(NR_+0)*T_ + t) * D_);
    const float4* s1 = (const float4*)(y + ((size_t)(NR_+1)*T_ + t) * D_);
    const float4* y1 = (const float4*)(y + ((size_t)e1*T_ + p1) * D_);
    const float4* y2 = (const float4*)(y + ((size_t)e2*T_ + p2) * D_);
    float4* op = (float4*)(out + (size_t)t * D_);
    for (int d = tid; d < D_/4; d += blockDim.x) {
        float4 o = op[d];
        float4 a = s0[d], b = s1[d], c = y1[d], e = y2[d];
        o.x += a.x + b.x + w1*c.x + w2*e.x;
        o.y += a.y + b.y + w1*c.y + w2*e.y;
        o.z += a.z + b.z + w1*c.z + w2*e.z;
        o.w += a.w + b.w + w1*c.w + w2*e.w;
        op[d] = o;
    }
}

// ---------------- launch ---------------------------------------------------
extern "C" void kernel_launch(void* const* d_in, const int* in_sizes, int n_in,
                              void* d_out, int out_size) {
    const float* x         = (const float*)d_in[0];
    const float* w_q       = (const float*)d_in[2];
    const float* w_dkv     = (const float*)d_in[3];
    const float* w_uk      = (const float*)d_in[4];
    const float* w_uv      = (const float*)d_in[5];
    const float* w_kr      = (const float*)d_in[6];
    const float* w_o       = (const float*)d_in[7];
    const float* attn_nw   = (const float*)d_in[8];
    const float* mlp_nw    = (const float*)d_in[9];
    const float* gate_w    = (const float*)d_in[10];
    const float* wr_gate   = (const float*)d_in[11];
    const float* wr_up     = (const float*)d_in[12];
    const float* wr_down   = (const float*)d_in[13];
    const float* ws_gate   = (const float*)d_in[14];
    const float* ws_up     = (const float*)d_in[15];
    const float* ws_down   = (const float*)d_in[16];
    float* out = (float*)d_out;

    float *ph, *pq, *plat, *pkc, *pv, *pkr, *pctx, *ph2;
    float *pgb, *py, *prw;
    int *pcnt, *pel, *prt;
    cudaGetSymbolAddress((void**)&ph,   g_h);
    cudaGetSymbolAddress((void**)&pq,   g_q);
    cudaGetSymbolAddress((void**)&plat, g_lat);
    cudaGetSymbolAddress((void**)&pkc,  g_kc);
    cudaGetSymbolAddress((void**)&pv,   g_v);
    cudaGetSymbolAddress((void**)&pkr,  g_kr);
    cudaGetSymbolAddress((void**)&pctx, g_ctx);
    cudaGetSymbolAddress((void**)&ph2,  g_h2);
    cudaGetSymbolAddress((void**)&pgb,  g_gb);
    cudaGetSymbolAddress((void**)&py,   g_y);
    cudaGetSymbolAddress((void**)&pcnt, g_cnt);
    cudaGetSymbolAddress((void**)&pel,  g_elist);
    cudaGetSymbolAddress((void**)&prt,  g_rt);
    cudaGetSymbolAddress((void**)&prw,  g_rw);

    cudaFuncSetAttribute(flash_mma_k,
                         cudaFuncAttributeMaxDynamicSharedMemorySize, FA_SMEM_BYTES);
    cudaFuncSetAttribute(mma_multi4,
                         cudaFuncAttributeMaxDynamicSharedMemorySize, MM_SMEM_BYTES);
    cudaFuncSetAttribute(mma_gu_all,
                         cudaFuncAttributeMaxDynamicSharedMemorySize, MM_SMEM_BYTES);
    cudaFuncSetAttribute(mma_down_all,
                         cudaFuncAttributeMaxDynamicSharedMemorySize, MM_SMEM_BYTES);

    // 1) h = rmsnorm(x)
    rmsnorm_k<<<T_, 256>>>(x, attn_nw, ph);

    // 2) fused projections: w_q (16 tiles) + w_dkv (4) + w_kr (1)
    mma_multi4<<<dim3(21, T_/128), 256, MM_SMEM_BYTES>>>(ph, D_,
        w_q,   pq,   H_*QDIM_, 16,
        w_dkv, plat, DL_,      4,
        w_kr,  pkr,  DR_,      1,
        nullptr, nullptr, 0, 0, nullptr);

    // 3) RoPE
    {
        int n = T_*H_*32 + T_*32;
        rope_k<<<(n + 255)/256, 256>>>(pq, pkr);
    }

    // 4) fused k_c + v up-projections
    mma_multi4<<<dim3(16, T_/128), 256, MM_SMEM_BYTES>>>(plat, DL_,
        w_uk, pkc, H_*DH_, 8,
        w_uv, pv,  H_*DH_, 8,
        nullptr, nullptr, 0, 0,
        nullptr, nullptr, 0, 0, nullptr);

    // 5) attention (64 q-rows/CTA, longest-first CTA order)
    flash_mma_k<<<dim3(S_/64, B_*H_), 128, FA_SMEM_BYTES>>>(pq, pkc, pkr, pv, pctx);

    // 6) out = x + ctx @ w_o
    mma_multi4<<<dim3(8, T_/128), 256, MM_SMEM_BYTES>>>(pctx, H_*DH_,
        w_o, out, D_, 8,
        nullptr, nullptr, 0, 0,
        nullptr, nullptr, 0, 0,
        nullptr, nullptr, 0, 0, x);

    // 7) h2 = rmsnorm(out)
    rmsnorm_k<<<T_, 256>>>(out, mlp_nw, ph2);

    // 8) routing
    zero_cnt_k<<<1, 32>>>(pcnt);
    gate_topk_k<<<T_/8, 256>>>(ph2, gate_w, pcnt, pel, prt, prw);

    // 9) unified experts: fused gate+up+silu, then down (10 slices each)
    mma_gu_all<<<dim3(DHID_/64, T_/128, NE_), 256, MM_SMEM_BYTES>>>(
        ph2, wr_gate, wr_up, ws_gate, ws_up, pgb, pel, pcnt);
    mma_down_all<<<dim3(D_/128, T_/128, NE_), 256, MM_SMEM_BYTES>>>(
        pgb, wr_down, ws_down, py, pcnt);

    // 10) deterministic combine
    reduce_k<<<T_, 256>>>(out, py, prt, prw);
}